// round 14
// baseline (speedup 1.0000x reference)
#include <cuda_runtime.h>
#include <cuda_fp16.h>
#include <cstdint>

#define NN   50000
#define PP   4
#define EE   500000
#define IND  128
#define HH   8
#define FF   32
#define HFF  256
#define HSS  128
#define BB   128
#define OUTC 2
#define MSEM (PP * NN)
#define CH   1024
#define NCH  ((NN + CH - 1) / CH)    // 49
#define NBLK ((NN + 7) / 8)          // attn blocks per metapath: 6250

// ---------------- persistent device scratch ----------------
__device__ __half    g_hp16[PP * NN * HFF];
__device__ __half    g_z16[PP * NN * HFF];
__device__ __half    g_W1h[HSS * HFF];
__device__ __half    g_h16[NN * IND];          // h fp16 [m][k]
__device__ __half    g_wg16[PP * HFF * IND];   // Wg fp16 transposed [p][n][k]
__device__ float g_el[PP * NN * HH];
__device__ float g_er[PP * NN * HH];
__device__ int   g_deg[PP * NN];
__device__ int   g_off[PP * (NN + 1)];
__device__ int   g_cur[PP * NN];
__device__ int   g_csr[PP * EE];
__device__ int   g_bsum[PP * NCH];
__device__ int   g_boff[PP * NCH];
__device__ float g_wsum[PP];
__device__ float g_beta[PP];
__device__ float g_pooled[BB * HFF];
__device__ int   g_cnt[BB];

__device__ __forceinline__ float eluf(float x) {
    return x > 0.f ? x : (__expf(x) - 1.f);
}

__device__ __forceinline__ void mma_f16_k16(float* c, const uint32_t* a, const uint32_t* b) {
    asm volatile(
        "mma.sync.aligned.m16n8k16.row.col.f32.f16.f16.f32 "
        "{%0,%1,%2,%3},{%4,%5,%6,%7},{%8,%9},{%0,%1,%2,%3};"
        : "+f"(c[0]), "+f"(c[1]), "+f"(c[2]), "+f"(c[3])
        : "r"(a[0]), "r"(a[1]), "r"(a[2]), "r"(a[3]), "r"(b[0]), "r"(b[1]));
}

__device__ __forceinline__ void ldsm_x4(uint32_t* r, uint32_t addr) {
    asm volatile("ldmatrix.sync.aligned.m8n8.x4.shared.b16 {%0,%1,%2,%3}, [%4];"
        : "=r"(r[0]), "=r"(r[1]), "=r"(r[2]), "=r"(r[3]) : "r"(addr));
}

__device__ __forceinline__ uint32_t smem_u32(const void* p) {
    uint32_t a;
    asm("{ .reg .u64 t; cvta.to.shared.u64 t, %1; cvt.u32.u64 %0, t; }" : "=r"(a) : "l"(p));
    return a;
}

// ---------------- init (zeroing ONLY) ----------------
__global__ void zero_kernel() {
    int i = blockIdx.x * blockDim.x + threadIdx.x;
    if (i < PP * NN)  g_deg[i] = 0;
    if (i < BB * HFF) g_pooled[i] = 0.f;
    if (i < BB)       g_cnt[i] = 0;
    if (i < PP)       g_wsum[i] = 0.f;
}

// ---------------- pre-convert h, Wg (transposed), W1 (transposed) to fp16 ----------------
#define CVT_T1 (NN * IND / 4)
#define CVT_T2 (PP * IND * HFF)
#define CVT_T3 (HFF * HSS)
__global__ void cvt_kernel(const float* __restrict__ h, const float* __restrict__ Wg,
                           const float* __restrict__ W1) {
    int i = blockIdx.x * blockDim.x + threadIdx.x;
    if (i < CVT_T1) {
        float4 v = *(const float4*)(h + (size_t)i * 4);
        uint2 u;
        *(__half2*)&u.x = __floats2half2_rn(v.x, v.y);
        *(__half2*)&u.y = __floats2half2_rn(v.z, v.w);
        *(uint2*)(g_h16 + (size_t)i * 4) = u;
    } else if (i < CVT_T1 + CVT_T2) {
        int j = i - CVT_T1;
        int k = j % IND;
        int pn = j / IND;
        int n = pn % HFF;
        int p = pn / HFF;
        g_wg16[j] = __float2half(Wg[((size_t)p * IND + k) * HFF + n]);
    } else if (i < CVT_T1 + CVT_T2 + CVT_T3) {
        int j = i - CVT_T1 - CVT_T2;       // j = k*HSS + n
        int k = j / HSS, n = j % HSS;
        g_W1h[n * HFF + k] = __float2half(W1[j]);
    }
}

// ---------------- projection GEMM fp16 HMMA (LDSM fragments + prefetch) ----------------
__global__ __launch_bounds__(256, 2) void gemm_proj_tc(const float* __restrict__ al,
                                                       const float* __restrict__ ar) {
    int p = blockIdx.z;
    const __half* B = g_wg16 + (size_t)p * HFF * IND;
    __half* C = g_hp16 + (size_t)p * NN * HFF;

    __shared__ uint32_t As[128][12];
    __shared__ uint32_t Bs[128][12];

    int tid = threadIdx.x;
    int warp = tid >> 5, lane = tid & 31;
    int group = lane >> 2, tid4 = lane & 3;
    int warp_m = (warp >> 2) * 64, warp_n = (warp & 3) * 32;
    int m0 = blockIdx.x * 128, n0 = blockIdx.y * 128;

    int mA = tid >> 1, kHalf = (tid & 1) << 3;

    float acc[4][4][4] = {};

    int rowA = m0 + mA;  if (rowA >= NN) rowA = NN - 1;
    const __half* aPtr = g_h16 + (size_t)rowA * IND + kHalf;
    const __half* bPtr = B + (size_t)(n0 + mA) * IND + kHalf;

    int a_lrow = lane & 15;
    int a_lcol = (lane >> 4) << 2;
    int b_lrow = (lane & 7) + ((lane >> 4) << 3);
    int b_lcol = (lane & 8) ? 4 : 0;
    uint32_t As_base = smem_u32(&As[0][0]);
    uint32_t Bs_base = smem_u32(&Bs[0][0]);

    uint4 av = *(const uint4*)(aPtr);
    uint4 bv = *(const uint4*)(bPtr);

    #pragma unroll
    for (int k0 = 0; k0 < IND; k0 += 16) {
        __syncthreads();
        *(uint4*)&As[mA][(tid & 1) << 2] = av;
        *(uint4*)&Bs[mA][(tid & 1) << 2] = bv;
        __syncthreads();
        if (k0 + 16 < IND) {
            av = *(const uint4*)(aPtr + k0 + 16);
            bv = *(const uint4*)(bPtr + k0 + 16);
        }
        uint32_t af[4][4], bf[4][2];
        #pragma unroll
        for (int mi = 0; mi < 4; mi++) {
            int r = warp_m + mi * 16 + a_lrow;
            ldsm_x4(af[mi], As_base + (uint32_t)(r * 12 + a_lcol) * 4u);
        }
        #pragma unroll
        for (int nj = 0; nj < 2; nj++) {
            uint32_t rr[4];
            int r = warp_n + nj * 16 + b_lrow;
            ldsm_x4(rr, Bs_base + (uint32_t)(r * 12 + b_lcol) * 4u);
            bf[2 * nj][0] = rr[0]; bf[2 * nj][1] = rr[1];
            bf[2 * nj + 1][0] = rr[2]; bf[2 * nj + 1][1] = rr[3];
        }
        #pragma unroll
        for (int mi = 0; mi < 4; mi++)
            #pragma unroll
            for (int ni = 0; ni < 4; ni++)
                mma_f16_k16(acc[mi][ni], af[mi], bf[ni]);
    }

    // store hp as fp16
    #pragma unroll
    for (int mi = 0; mi < 4; mi++) {
        int r_lo = m0 + warp_m + mi * 16 + group;
        #pragma unroll
        for (int ni = 0; ni < 4; ni++) {
            int col = n0 + warp_n + ni * 8 + (tid4 << 1);
            if (r_lo < NN) {
                __half2 o = __floats2half2_rn(acc[mi][ni][0], acc[mi][ni][1]);
                *(__half2*)(C + (size_t)r_lo * HFF + col) = o;
            }
            if (r_lo + 8 < NN) {
                __half2 o = __floats2half2_rn(acc[mi][ni][2], acc[mi][ni][3]);
                *(__half2*)(C + (size_t)(r_lo + 8) * HFF + col) = o;
            }
        }
    }

    // fused el/er epilogue: this warp's head
    int head = blockIdx.y * 4 + (warp_n >> 5);
    const float* alh = al + p * HFF + head * FF;
    const float* arh = ar + p * HFF + head * FF;
    #pragma unroll
    for (int mi = 0; mi < 4; mi++) {
        float el_lo = 0.f, el_hi = 0.f, er_lo = 0.f, er_hi = 0.f;
        #pragma unroll
        for (int ni = 0; ni < 4; ni++) {
            int f = ni * 8 + (tid4 << 1);
            float a0 = alh[f], a1 = alh[f + 1];
            float r0 = arh[f], r1 = arh[f + 1];
            el_lo += acc[mi][ni][0] * a0 + acc[mi][ni][1] * a1;
            er_lo += acc[mi][ni][0] * r0 + acc[mi][ni][1] * r1;
            el_hi += acc[mi][ni][2] * a0 + acc[mi][ni][3] * a1;
            er_hi += acc[mi][ni][2] * r0 + acc[mi][ni][3] * r1;
        }
        #pragma unroll
        for (int d = 1; d < 4; d <<= 1) {
            el_lo += __shfl_xor_sync(0xffffffffu, el_lo, d);
            er_lo += __shfl_xor_sync(0xffffffffu, er_lo, d);
            el_hi += __shfl_xor_sync(0xffffffffu, el_hi, d);
            er_hi += __shfl_xor_sync(0xffffffffu, er_hi, d);
        }
        if (tid4 == 0) {
            int r = m0 + warp_m + mi * 16 + group;
            if (r < NN) {
                g_el[((size_t)p * NN + r) * HH + head] = el_lo;
                g_er[((size_t)p * NN + r) * HH + head] = er_lo;
            }
            if (r + 8 < NN) {
                g_el[((size_t)p * NN + r + 8) * HH + head] = el_hi;
                g_er[((size_t)p * NN + r + 8) * HH + head] = er_hi;
            }
        }
    }
}

// ---------------- CSR build (+ safe g_cnt accumulation) ----------------
__global__ void deg_kernel(const int* __restrict__ dst, const int* __restrict__ gids) {
    int i = blockIdx.x * blockDim.x + threadIdx.x;
    int p = blockIdx.y;
    if (p == 0 && i < NN) atomicAdd(&g_cnt[gids[i]], 1);
    if (i >= EE) return;
    atomicAdd(&g_deg[p * NN + dst[p * EE + i]], 1);
}

__global__ void bsum_kernel() {
    __shared__ int sred[256];
    int b = blockIdx.x;
    int p = b / NCH, c = b % NCH;
    int base = c * CH;
    int tid = threadIdx.x;
    int s = 0;
    #pragma unroll
    for (int j = 0; j < CH; j += 256) {
        int i = base + j + tid;
        if (i < NN) s += g_deg[p * NN + i];
    }
    sred[tid] = s;
    __syncthreads();
    for (int d = 128; d > 0; d >>= 1) {
        if (tid < d) sred[tid] += sred[tid + d];
        __syncthreads();
    }
    if (tid == 0) g_bsum[b] = sred[0];
}

__global__ void bscan_kernel() {
    int p = threadIdx.x;
    if (p < PP) {
        int run = 0;
        for (int c = 0; c < NCH; c++) {
            g_boff[p * NCH + c] = run;
            run += g_bsum[p * NCH + c];
        }
    }
}

__global__ void cscan_kernel() {
    __shared__ int wsums[32];
    int b = blockIdx.x;
    int p = b / NCH, c = b % NCH;
    int tid = threadIdx.x, lane = tid & 31, wid = tid >> 5;
    int i = c * CH + tid;
    int v = (i < NN) ? g_deg[p * NN + i] : 0;
    int x = v;
    #pragma unroll
    for (int d = 1; d < 32; d <<= 1) {
        int t2 = __shfl_up_sync(0xffffffffu, x, d);
        if (lane >= d) x += t2;
    }
    if (lane == 31) wsums[wid] = x;
    __syncthreads();
    if (wid == 0) {
        int y = wsums[lane];
        #pragma unroll
        for (int d = 1; d < 32; d <<= 1) {
            int t2 = __shfl_up_sync(0xffffffffu, y, d);
            if (lane >= d) y += t2;
        }
        wsums[lane] = y;
    }
    __syncthreads();
    int incl = x + (wid ? wsums[wid - 1] : 0) + g_boff[b];
    if (i < NN) {
        g_off[p * (NN + 1) + i + 1] = incl;
        g_cur[p * NN + i] = incl - v;
    }
    if (tid == 0 && c == 0) g_off[p * (NN + 1)] = 0;
}

__global__ void fill_kernel(const int* __restrict__ src, const int* __restrict__ dst) {
    int i = blockIdx.x * blockDim.x + threadIdx.x;
    int p = blockIdx.y;
    if (i >= EE) return;
    int d = dst[p * EE + i];
    int slot = atomicAdd(&g_cur[p * NN + d], 1);
    g_csr[p * EE + slot] = src[p * EE + i];
}

// ---------------- GAT edge softmax + aggregation (unroll x2 + index prefetch) -----------
__global__ __launch_bounds__(256) void attn_kernel(const float* __restrict__ bias) {
    int lane = threadIdx.x & 31;
    int v = blockIdx.x * 8 + (threadIdx.x >> 5);
    if (v >= NN) return;
    int p = blockIdx.y;
    int beg = g_off[p * (NN + 1) + v];
    int end = g_off[p * (NN + 1) + v + 1];
    const float*  __restrict__ elp = g_el + (size_t)p * NN * HH;
    const __half* __restrict__ hpp = g_hp16 + (size_t)p * NN * HFF;
    const int*    __restrict__ csr = g_csr + (size_t)p * EE;
    float er_l = 0.f;
    if (lane < HH) er_l = g_er[((size_t)p * NN + v) * HH + lane];
    int h = lane >> 2;
    float den = 0.f;
    float acc[8] = {};
    int i = beg;
    // prefetch first pair of indices
    int sA = 0, sB = 0;
    if (i + 1 < end) { sA = csr[i]; sB = csr[i + 1]; }
    for (; i + 1 < end; i += 2) {
        int s0 = sA, s1 = sB;
        if (i + 3 < end) { sA = csr[i + 2]; sB = csr[i + 3]; }   // overlaps current gathers
        float a0v = 0.f, a1v = 0.f;
        if (lane < HH) {
            float e0 = elp[(size_t)s0 * HH + lane] + er_l;
            float e1 = elp[(size_t)s1 * HH + lane] + er_l;
            e0 = e0 > 0.f ? e0 : 0.2f * e0;
            e1 = e1 > 0.f ? e1 : 0.2f * e1;
            a0v = __expf(e0);
            a1v = __expf(e1);
            den += a0v + a1v;
        }
        float ah0 = __shfl_sync(0xffffffffu, a0v, h);
        float ah1 = __shfl_sync(0xffffffffu, a1v, h);
        uint4 r0 = *(const uint4*)(hpp + (size_t)s0 * HFF + (lane << 3));
        uint4 r1 = *(const uint4*)(hpp + (size_t)s1 * HFF + (lane << 3));
        float2 p0 = __half22float2(*(__half2*)&r0.x);
        float2 p1 = __half22float2(*(__half2*)&r0.y);
        float2 p2 = __half22float2(*(__half2*)&r0.z);
        float2 p3 = __half22float2(*(__half2*)&r0.w);
        acc[0] += ah0 * p0.x; acc[1] += ah0 * p0.y;
        acc[2] += ah0 * p1.x; acc[3] += ah0 * p1.y;
        acc[4] += ah0 * p2.x; acc[5] += ah0 * p2.y;
        acc[6] += ah0 * p3.x; acc[7] += ah0 * p3.y;
        float2 q0 = __half22float2(*(__half2*)&r1.x);
        float2 q1 = __half22float2(*(__half2*)&r1.y);
        float2 q2 = __half22float2(*(__half2*)&r1.z);
        float2 q3 = __half22float2(*(__half2*)&r1.w);
        acc[0] += ah1 * q0.x; acc[1] += ah1 * q0.y;
        acc[2] += ah1 * q1.x; acc[3] += ah1 * q1.y;
        acc[4] += ah1 * q2.x; acc[5] += ah1 * q2.y;
        acc[6] += ah1 * q3.x; acc[7] += ah1 * q3.y;
    }
    if (i < end) {
        int s = csr[i];
        float a = 0.f;
        if (lane < HH) {
            float e = elp[(size_t)s * HH + lane] + er_l;
            e = e > 0.f ? e : 0.2f * e;
            a = __expf(e);
            den += a;
        }
        float ah = __shfl_sync(0xffffffffu, a, h);
        uint4 raw = *(const uint4*)(hpp + (size_t)s * HFF + (lane << 3));
        float2 f0 = __half22float2(*(__half2*)&raw.x);
        float2 f1 = __half22float2(*(__half2*)&raw.y);
        float2 f2 = __half22float2(*(__half2*)&raw.z);
        float2 f3 = __half22float2(*(__half2*)&raw.w);
        acc[0] += ah * f0.x; acc[1] += ah * f0.y;
        acc[2] += ah * f1.x; acc[3] += ah * f1.y;
        acc[4] += ah * f2.x; acc[5] += ah * f2.y;
        acc[6] += ah * f3.x; acc[7] += ah * f3.y;
    }
    float dh = __shfl_sync(0xffffffffu, den, h);
    float inv = (end > beg) ? 1.f / dh : 0.f;
    const float* bp = bias + p * HFF + (lane << 3);
    float4 b0 = *(const float4*)(bp);
    float4 b1 = *(const float4*)(bp + 4);
    float o0 = eluf(acc[0] * inv + b0.x);
    float o1 = eluf(acc[1] * inv + b0.y);
    float o2 = eluf(acc[2] * inv + b0.z);
    float o3 = eluf(acc[3] * inv + b0.w);
    float o4 = eluf(acc[4] * inv + b1.x);
    float o5 = eluf(acc[5] * inv + b1.y);
    float o6 = eluf(acc[6] * inv + b1.z);
    float o7 = eluf(acc[7] * inv + b1.w);
    uint4 out;
    *(__half2*)&out.x = __floats2half2_rn(o0, o1);
    *(__half2*)&out.y = __floats2half2_rn(o2, o3);
    *(__half2*)&out.z = __floats2half2_rn(o4, o5);
    *(__half2*)&out.w = __floats2half2_rn(o6, o7);
    *(uint4*)(g_z16 + ((size_t)p * NN + v) * HFF + (lane << 3)) = out;
}

// ---------------- semantic attention GEMM (fp16 HMMA, LDSM + prefetch) ----------
__global__ __launch_bounds__(256, 2) void gemm_sem_f16(const float* __restrict__ b1,
                                                       const float* __restrict__ W2) {
    __shared__ uint32_t As[128][12];
    __shared__ uint32_t Bs[128][12];
    __shared__ float spsum[PP];

    int tid = threadIdx.x;
    int warp = tid >> 5, lane = tid & 31;
    int group = lane >> 2, tid4 = lane & 3;
    int warp_m = (warp >> 2) * 64, warp_n = (warp & 3) * 32;
    int m0 = blockIdx.x * 128;

    if (tid < PP) spsum[tid] = 0.f;

    int mA = tid >> 1, kHalf = (tid & 1) << 3;

    float acc[4][4][4] = {};

    int rowA = m0 + mA;  if (rowA >= MSEM) rowA = MSEM - 1;
    const __half* aPtr = g_z16 + (size_t)rowA * HFF + kHalf;
    const __half* bPtr = g_W1h + (size_t)mA * HFF + kHalf;

    int a_lrow = lane & 15;
    int a_lcol = (lane >> 4) << 2;
    int b_lrow = (lane & 7) + ((lane >> 4) << 3);
    int b_lcol = (lane & 8) ? 4 : 0;
    uint32_t As_base = smem_u32(&As[0][0]);
    uint32_t Bs_base = smem_u32(&Bs[0][0]);

    uint4 av = *(const uint4*)(aPtr);
    uint4 bv = *(const uint4*)(bPtr);

    #pragma unroll
    for (int k0 = 0; k0 < HFF; k0 += 16) {
        __syncthreads();
        *(uint4*)&As[mA][(tid & 1) << 2] = av;
        *(uint4*)&Bs[mA][(tid & 1) << 2] = bv;
        __syncthreads();
        if (k0 + 16 < HFF) {
            av = *(const uint4*)(aPtr + k0 + 16);
            bv = *(const uint4*)(bPtr + k0 + 16);
        }
        uint32_t af[4][4], bf[4][2];
        #pragma unroll
        for (int mi = 0; mi < 4; mi++) {
            int r = warp_m + mi * 16 + a_lrow;
            ldsm_x4(af[mi], As_base + (uint32_t)(r * 12 + a_lcol) * 4u);
        }
        #pragma unroll
        for (int nj = 0; nj < 2; nj++) {
            uint32_t rr[4];
            int r = warp_n + nj * 16 + b_lrow;
            ldsm_x4(rr, Bs_base + (uint32_t)(r * 12 + b_lcol) * 4u);
            bf[2 * nj][0] = rr[0]; bf[2 * nj][1] = rr[1];
            bf[2 * nj + 1][0] = rr[2]; bf[2 * nj + 1][1] = rr[3];
        }
        #pragma unroll
        for (int mi = 0; mi < 4; mi++)
            #pragma unroll
            for (int ni = 0; ni < 4; ni++)
                mma_f16_k16(acc[mi][ni], af[mi], bf[ni]);
    }

    #pragma unroll
    for (int mi = 0; mi < 4; mi++) {
        float s_lo = 0.f, s_hi = 0.f;
        #pragma unroll
        for (int ni = 0; ni < 4; ni++) {
            int col = warp_n + ni * 8 + (tid4 << 1);
            float bb0 = b1[col], bb1 = b1[col + 1];
            float w0 = W2[col], w1 = W2[col + 1];
            s_lo += tanhf(acc[mi][ni][0] + bb0) * w0 + tanhf(acc[mi][ni][1] + bb1) * w1;
            s_hi += tanhf(acc[mi][ni][2] + bb0) * w0 + tanhf(acc[mi][ni][3] + bb1) * w1;
        }
        #pragma unroll
        for (int d = 1; d < 4; d <<= 1) {
            s_lo += __shfl_xor_sync(0xffffffffu, s_lo, d);
            s_hi += __shfl_xor_sync(0xffffffffu, s_hi, d);
        }
        if (tid4 == 0) {
            int r = m0 + warp_m + mi * 16 + group;
            if (r < MSEM)     atomicAdd(&spsum[r / NN], s_lo);
            if (r + 8 < MSEM) atomicAdd(&spsum[(r + 8) / NN], s_hi);
        }
    }
    __syncthreads();
    if (tid < PP) atomicAdd(&g_wsum[tid], spsum[tid]);
}

// ---------------- beta softmax ----------------
__global__ void beta_kernel() {
    if (threadIdx.x == 0 && blockIdx.x == 0) {
        float w[PP], m = -1e30f, s = 0.f;
        #pragma unroll
        for (int p = 0; p < PP; p++) { w[p] = g_wsum[p] / (float)NN; m = fmaxf(m, w[p]); }
        #pragma unroll
        for (int p = 0; p < PP; p++) { w[p] = __expf(w[p] - m); s += w[p]; }
        #pragma unroll
        for (int p = 0; p < PP; p++) g_beta[p] = w[p] / s;
    }
}

// ---------------- fused embedding + per-graph pooling (smem-binned) ----------------
#define POOL_CHUNK 1024
__global__ __launch_bounds__(256) void pool_kernel(const int* __restrict__ gids) {
    __shared__ float bin[BB][64];
    int tid = threadIdx.x;
    int cy = blockIdx.y;
    int n0 = blockIdx.x * POOL_CHUNK;
    #pragma unroll
    for (int k = tid; k < BB * 64; k += 256) ((float*)bin)[k] = 0.f;
    __syncthreads();
    float bb0 = g_beta[0], bb1 = g_beta[1], bb2 = g_beta[2], bb3 = g_beta[3];
    int c = (tid & 15) << 2;
    int colg = cy * 64 + c;
    int nend = n0 + POOL_CHUNK; if (nend > NN) nend = NN;
    for (int n = n0 + (tid >> 4); n < nend; n += 16) {
        int g = gids[n];
        uint2 r0 = *(const uint2*)(g_z16 + ((size_t)0 * NN + n) * HFF + colg);
        uint2 r1 = *(const uint2*)(g_z16 + ((size_t)1 * NN + n) * HFF + colg);
        uint2 r2 = *(const uint2*)(g_z16 + ((size_t)2 * NN + n) * HFF + colg);
        uint2 r3 = *(const uint2*)(g_z16 + ((size_t)3 * NN + n) * HFF + colg);
        float2 a0 = __half22float2(*(__half2*)&r0.x), a1 = __half22float2(*(__half2*)&r0.y);
        float2 b0 = __half22float2(*(__half2*)&r1.x), b1 = __half22float2(*(__half2*)&r1.y);
        float2 c0 = __half22float2(*(__half2*)&r2.x), c1 = __half22float2(*(__half2*)&r2.y);
        float2 d0 = __half22float2(*(__half2*)&r3.x), d1 = __half22float2(*(__half2*)&r3.y);
        float f0 = bb0 * a0.x + bb1 * b0.x + bb2 * c0.x + bb3 * d0.x;
        float f1 = bb0 * a0.y + bb1 * b0.y + bb2 * c0.y + bb3 * d0.y;
        float f2 = bb0 * a1.x + bb1 * b1.x + bb2 * c1.x + bb3 * d1.x;
        float f3 = bb0 * a1.y + bb1 * b1.y + bb2 * c1.y + bb3 * d1.y;
        atomicAdd(&bin[g][c + 0], f0);
        atomicAdd(&bin[g][c + 1], f1);
        atomicAdd(&bin[g][c + 2], f2);
        atomicAdd(&bin[g][c + 3], f3);
    }
    __syncthreads();
    for (int k = tid; k < BB * 64; k += 256) {
        int g = k >> 6, cc = k & 63;
        float v = bin[g][cc];
        if (v != 0.f) atomicAdd(&g_pooled[g * HFF + cy * 64 + cc], v);
    }
}

// ---------------- pooled normalize + classifier ----------------
__global__ __launch_bounds__(256) void final_kernel(const float* __restrict__ clsW,
                                                    const float* __restrict__ clsb,
                                                    float* __restrict__ out) {
    int g = blockIdx.x;
    int t = threadIdx.x;
    float cnt = (float)g_cnt[g];
    float inv = 1.f / fmaxf(cnt, 1.f);
    float pv = g_pooled[g * HFF + t] * inv;
    out[BB * OUTC + g * HFF + t] = pv;
    __shared__ float s0[256], s1[256];
    s0[t] = pv * clsW[t * OUTC + 0];
    s1[t] = pv * clsW[t * OUTC + 1];
    __syncthreads();
    for (int d = 128; d > 0; d >>= 1) {
        if (t < d) { s0[t] += s0[t + d]; s1[t] += s1[t + d]; }
        __syncthreads();
    }
    if (t == 0) {
        out[g * OUTC + 0] = s0[0] + clsb[0];
        out[g * OUTC + 1] = s1[0] + clsb[1];
    }
}

// ---------------- launch ----------------
extern "C" void kernel_launch(void* const* d_in, const int* in_sizes, int n_in,
                              void* d_out, int out_size) {
    const float* h    = (const float*)d_in[0];
    const float* Wg   = (const float*)d_in[1];
    const float* al   = (const float*)d_in[2];
    const float* ar   = (const float*)d_in[3];
    const float* gb   = (const float*)d_in[4];
    const float* sW1  = (const float*)d_in[5];
    const float* sb1  = (const float*)d_in[6];
    const float* sW2  = (const float*)d_in[7];
    const float* cW   = (const float*)d_in[8];
    const float* cb   = (const float*)d_in[9];
    const int*   src  = (const int*)d_in[10];
    const int*   dst  = (const int*)d_in[11];
    const int*   gid  = (const int*)d_in[12];
    float* out = (float*)d_out;

    zero_kernel<<<(PP * NN + 255) / 256, 256>>>();
    cvt_kernel<<<(CVT_T1 + CVT_T2 + CVT_T3 + 255) / 256, 256>>>(h, Wg, sW1);
    dim3 gd((EE + 255) / 256, PP);
    deg_kernel<<<gd, 256>>>(dst, gid);

    dim3 gp((NN + 127) / 128, 2, PP);
    gemm_proj_tc<<<gp, 256>>>(al, ar);                              // profiled slot

    bsum_kernel<<<PP * NCH, 256>>>();
    bscan_kernel<<<1, 32>>>();
    cscan_kernel<<<PP * NCH, CH>>>();
    fill_kernel<<<gd, 256>>>(src, dst);

    dim3 ga(NBLK, PP);
    attn_kernel<<<ga, 256>>>(gb);

    dim3 gs((MSEM + 127) / 128, 1);
    gemm_sem_f16<<<gs, 256>>>(sb1, sW2);

    beta_kernel<<<1, 32>>>();
    dim3 gpool((NN + POOL_CHUNK - 1) / POOL_CHUNK, 4);
    pool_kernel<<<gpool, 256>>>(gid);
    final_kernel<<<BB, 256>>>(cW, cb, out);
}

// round 15
// speedup vs baseline: 1.0221x; 1.0221x over previous
#include <cuda_runtime.h>
#include <cuda_fp16.h>
#include <cstdint>

#define NN   50000
#define PP   4
#define EE   500000
#define IND  128
#define HH   8
#define FF   32
#define HFF  256
#define HSS  128
#define BB   128
#define OUTC 2
#define MSEM (PP * NN)
#define CH   1024
#define NCH  ((NN + CH - 1) / CH)    // 49
#define NBLK ((NN + 7) / 8)
#define GPX  ((NN + 127) / 128)      // proj grid x: 391

// ---------------- persistent device scratch ----------------
__device__ __half    g_hp16[PP * NN * HFF];
__device__ __half    g_z16[PP * NN * HFF];
__device__ __half    g_W1h[HSS * HFF];
__device__ __half    g_h16[NN * IND];
__device__ __half    g_wg16[PP * HFF * IND];
__device__ float g_el[PP * NN * HH];
__device__ float g_er[PP * NN * HH];
__device__ int   g_deg[PP * NN];
__device__ int   g_off[PP * (NN + 1)];
__device__ int   g_cur[PP * NN];
__device__ int   g_csr[PP * EE];
__device__ int   g_bsum[PP * NCH];
__device__ int   g_boff[PP * NCH];
__device__ float g_wsum[PP];
__device__ float g_beta[PP];
__device__ float g_pooled[BB * HFF];
__device__ int   g_cnt[BB];

__device__ __forceinline__ float eluf(float x) {
    return x > 0.f ? x : (__expf(x) - 1.f);
}

__device__ __forceinline__ void mma_f16_k16(float* c, const uint32_t* a, const uint32_t* b) {
    asm volatile(
        "mma.sync.aligned.m16n8k16.row.col.f32.f16.f16.f32 "
        "{%0,%1,%2,%3},{%4,%5,%6,%7},{%8,%9},{%0,%1,%2,%3};"
        : "+f"(c[0]), "+f"(c[1]), "+f"(c[2]), "+f"(c[3])
        : "r"(a[0]), "r"(a[1]), "r"(a[2]), "r"(a[3]), "r"(b[0]), "r"(b[1]));
}

__device__ __forceinline__ void ldsm_x4(uint32_t* r, uint32_t addr) {
    asm volatile("ldmatrix.sync.aligned.m8n8.x4.shared.b16 {%0,%1,%2,%3}, [%4];"
        : "=r"(r[0]), "=r"(r[1]), "=r"(r[2]), "=r"(r[3]) : "r"(addr));
}

__device__ __forceinline__ uint32_t smem_u32(const void* p) {
    uint32_t a;
    asm("{ .reg .u64 t; cvta.to.shared.u64 t, %1; cvt.u32.u64 %0, t; }" : "=r"(a) : "l"(p));
    return a;
}

// ---------------- fused init + precision conversion ----------------
// zero ranges are disjoint from cvt ranges; all must finish before gemm_proj launch.
#define CVT_T1 (NN * IND / 4)
#define CVT_T2 (PP * IND * HFF)
#define CVT_T3 (HFF * HSS)
#define CVT_T4 (PP * NN)             // zero g_deg + small arrays
__global__ void cvt_zero_kernel(const float* __restrict__ h, const float* __restrict__ Wg,
                                const float* __restrict__ W1) {
    int i = blockIdx.x * blockDim.x + threadIdx.x;
    if (i < CVT_T1) {
        float4 v = *(const float4*)(h + (size_t)i * 4);
        uint2 u;
        *(__half2*)&u.x = __floats2half2_rn(v.x, v.y);
        *(__half2*)&u.y = __floats2half2_rn(v.z, v.w);
        *(uint2*)(g_h16 + (size_t)i * 4) = u;
    } else if (i < CVT_T1 + CVT_T2) {
        int j = i - CVT_T1;
        int k = j % IND;
        int pn = j / IND;
        int n = pn % HFF;
        int p = pn / HFF;
        g_wg16[j] = __float2half(Wg[((size_t)p * IND + k) * HFF + n]);
    } else if (i < CVT_T1 + CVT_T2 + CVT_T3) {
        int j = i - CVT_T1 - CVT_T2;
        int k = j / HSS, n = j % HSS;
        g_W1h[n * HFF + k] = __float2half(W1[j]);
    } else if (i < CVT_T1 + CVT_T2 + CVT_T3 + CVT_T4) {
        int j = i - CVT_T1 - CVT_T2 - CVT_T3;
        g_deg[j] = 0;
        if (j < BB * HFF) g_pooled[j] = 0.f;
        if (j < BB)       g_cnt[j] = 0;
        if (j < PP)       g_wsum[j] = 0.f;
    }
}

// ---------------- projection GEMM fp16 HMMA + FUSED deg/cnt blocks ----------------
// grid (GPX, 2, PP+1): z<PP -> GEMM tile; z==PP -> degree-count backfill blocks.
__global__ __launch_bounds__(256, 2) void gemm_proj_tc(const float* __restrict__ al,
                                                       const float* __restrict__ ar,
                                                       const int* __restrict__ dst,
                                                       const int* __restrict__ gids) {
    if (blockIdx.z == PP) {
        // degree-count + graph-count backfill (memory-bound; hides under GEMM)
        int t = (blockIdx.y * gridDim.x + blockIdx.x) * 256 + threadIdx.x;
        int nthr = gridDim.x * 2 * 256;
        if (t < NN) atomicAdd(&g_cnt[gids[t]], 1);
        for (int i = t; i < PP * EE; i += nthr) {
            int p = i / EE;
            atomicAdd(&g_deg[p * NN + dst[i]], 1);
        }
        return;
    }
    int p = blockIdx.z;
    const __half* B = g_wg16 + (size_t)p * HFF * IND;
    __half* C = g_hp16 + (size_t)p * NN * HFF;

    __shared__ uint32_t As[128][12];
    __shared__ uint32_t Bs[128][12];

    int tid = threadIdx.x;
    int warp = tid >> 5, lane = tid & 31;
    int group = lane >> 2, tid4 = lane & 3;
    int warp_m = (warp >> 2) * 64, warp_n = (warp & 3) * 32;
    int m0 = blockIdx.x * 128, n0 = blockIdx.y * 128;

    int mA = tid >> 1, kHalf = (tid & 1) << 3;

    float acc[4][4][4] = {};

    int rowA = m0 + mA;  if (rowA >= NN) rowA = NN - 1;
    const __half* aPtr = g_h16 + (size_t)rowA * IND + kHalf;
    const __half* bPtr = B + (size_t)(n0 + mA) * IND + kHalf;

    int a_lrow = lane & 15;
    int a_lcol = (lane >> 4) << 2;
    int b_lrow = (lane & 7) + ((lane >> 4) << 3);
    int b_lcol = (lane & 8) ? 4 : 0;
    uint32_t As_base = smem_u32(&As[0][0]);
    uint32_t Bs_base = smem_u32(&Bs[0][0]);

    uint4 av = *(const uint4*)(aPtr);
    uint4 bv = *(const uint4*)(bPtr);

    #pragma unroll
    for (int k0 = 0; k0 < IND; k0 += 16) {
        __syncthreads();
        *(uint4*)&As[mA][(tid & 1) << 2] = av;
        *(uint4*)&Bs[mA][(tid & 1) << 2] = bv;
        __syncthreads();
        if (k0 + 16 < IND) {
            av = *(const uint4*)(aPtr + k0 + 16);
            bv = *(const uint4*)(bPtr + k0 + 16);
        }
        uint32_t af[4][4], bf[4][2];
        #pragma unroll
        for (int mi = 0; mi < 4; mi++) {
            int r = warp_m + mi * 16 + a_lrow;
            ldsm_x4(af[mi], As_base + (uint32_t)(r * 12 + a_lcol) * 4u);
        }
        #pragma unroll
        for (int nj = 0; nj < 2; nj++) {
            uint32_t rr[4];
            int r = warp_n + nj * 16 + b_lrow;
            ldsm_x4(rr, Bs_base + (uint32_t)(r * 12 + b_lcol) * 4u);
            bf[2 * nj][0] = rr[0]; bf[2 * nj][1] = rr[1];
            bf[2 * nj + 1][0] = rr[2]; bf[2 * nj + 1][1] = rr[3];
        }
        #pragma unroll
        for (int mi = 0; mi < 4; mi++)
            #pragma unroll
            for (int ni = 0; ni < 4; ni++)
                mma_f16_k16(acc[mi][ni], af[mi], bf[ni]);
    }

    // store hp as fp16
    #pragma unroll
    for (int mi = 0; mi < 4; mi++) {
        int r_lo = m0 + warp_m + mi * 16 + group;
        #pragma unroll
        for (int ni = 0; ni < 4; ni++) {
            int col = n0 + warp_n + ni * 8 + (tid4 << 1);
            if (r_lo < NN) {
                __half2 o = __floats2half2_rn(acc[mi][ni][0], acc[mi][ni][1]);
                *(__half2*)(C + (size_t)r_lo * HFF + col) = o;
            }
            if (r_lo + 8 < NN) {
                __half2 o = __floats2half2_rn(acc[mi][ni][2], acc[mi][ni][3]);
                *(__half2*)(C + (size_t)(r_lo + 8) * HFF + col) = o;
            }
        }
    }

    // fused el/er epilogue: this warp's head
    int head = blockIdx.y * 4 + (warp_n >> 5);
    const float* alh = al + p * HFF + head * FF;
    const float* arh = ar + p * HFF + head * FF;
    #pragma unroll
    for (int mi = 0; mi < 4; mi++) {
        float el_lo = 0.f, el_hi = 0.f, er_lo = 0.f, er_hi = 0.f;
        #pragma unroll
        for (int ni = 0; ni < 4; ni++) {
            int f = ni * 8 + (tid4 << 1);
            float a0 = alh[f], a1 = alh[f + 1];
            float r0 = arh[f], r1 = arh[f + 1];
            el_lo += acc[mi][ni][0] * a0 + acc[mi][ni][1] * a1;
            er_lo += acc[mi][ni][0] * r0 + acc[mi][ni][1] * r1;
            el_hi += acc[mi][ni][2] * a0 + acc[mi][ni][3] * a1;
            er_hi += acc[mi][ni][2] * r0 + acc[mi][ni][3] * r1;
        }
        #pragma unroll
        for (int d = 1; d < 4; d <<= 1) {
            el_lo += __shfl_xor_sync(0xffffffffu, el_lo, d);
            er_lo += __shfl_xor_sync(0xffffffffu, er_lo, d);
            el_hi += __shfl_xor_sync(0xffffffffu, el_hi, d);
            er_hi += __shfl_xor_sync(0xffffffffu, er_hi, d);
        }
        if (tid4 == 0) {
            int r = m0 + warp_m + mi * 16 + group;
            if (r < NN) {
                g_el[((size_t)p * NN + r) * HH + head] = el_lo;
                g_er[((size_t)p * NN + r) * HH + head] = er_lo;
            }
            if (r + 8 < NN) {
                g_el[((size_t)p * NN + r + 8) * HH + head] = el_hi;
                g_er[((size_t)p * NN + r + 8) * HH + head] = er_hi;
            }
        }
    }
}

// ---------------- CSR scan + fill ----------------
__global__ void bsum_kernel() {
    __shared__ int sred[256];
    int b = blockIdx.x;
    int p = b / NCH, c = b % NCH;
    int base = c * CH;
    int tid = threadIdx.x;
    int s = 0;
    #pragma unroll
    for (int j = 0; j < CH; j += 256) {
        int i = base + j + tid;
        if (i < NN) s += g_deg[p * NN + i];
    }
    sred[tid] = s;
    __syncthreads();
    for (int d = 128; d > 0; d >>= 1) {
        if (tid < d) sred[tid] += sred[tid + d];
        __syncthreads();
    }
    if (tid == 0) g_bsum[b] = sred[0];
}

__global__ void bscan_kernel() {
    int p = threadIdx.x;
    if (p < PP) {
        int run = 0;
        for (int c = 0; c < NCH; c++) {
            g_boff[p * NCH + c] = run;
            run += g_bsum[p * NCH + c];
        }
    }
}

__global__ void cscan_kernel() {
    __shared__ int wsums[32];
    int b = blockIdx.x;
    int p = b / NCH, c = b % NCH;
    int tid = threadIdx.x, lane = tid & 31, wid = tid >> 5;
    int i = c * CH + tid;
    int v = (i < NN) ? g_deg[p * NN + i] : 0;
    int x = v;
    #pragma unroll
    for (int d = 1; d < 32; d <<= 1) {
        int t2 = __shfl_up_sync(0xffffffffu, x, d);
        if (lane >= d) x += t2;
    }
    if (lane == 31) wsums[wid] = x;
    __syncthreads();
    if (wid == 0) {
        int y = wsums[lane];
        #pragma unroll
        for (int d = 1; d < 32; d <<= 1) {
            int t2 = __shfl_up_sync(0xffffffffu, y, d);
            if (lane >= d) y += t2;
        }
        wsums[lane] = y;
    }
    __syncthreads();
    int incl = x + (wid ? wsums[wid - 1] : 0) + g_boff[b];
    if (i < NN) {
        g_off[p * (NN + 1) + i + 1] = incl;
        g_cur[p * NN + i] = incl - v;
    }
    if (tid == 0 && c == 0) g_off[p * (NN + 1)] = 0;
}

__global__ void fill_kernel(const int* __restrict__ src, const int* __restrict__ dst) {
    int i = blockIdx.x * blockDim.x + threadIdx.x;
    int p = blockIdx.y;
    if (i >= EE) return;
    int d = dst[p * EE + i];
    int slot = atomicAdd(&g_cur[p * NN + d], 1);
    g_csr[p * EE + slot] = src[p * EE + i];
}

// ---------------- GAT edge softmax + aggregation (unroll x2, fp16 gather) ----------------
__global__ __launch_bounds__(256) void attn_kernel(const float* __restrict__ bias) {
    int lane = threadIdx.x & 31;
    int v = blockIdx.x * 8 + (threadIdx.x >> 5);
    if (v >= NN) return;
    int p = blockIdx.y;
    int beg = g_off[p * (NN + 1) + v];
    int end = g_off[p * (NN + 1) + v + 1];
    const float*  __restrict__ elp = g_el + (size_t)p * NN * HH;
    const __half* __restrict__ hpp = g_hp16 + (size_t)p * NN * HFF;
    const int*    __restrict__ csr = g_csr + (size_t)p * EE;
    float er_l = 0.f;
    if (lane < HH) er_l = g_er[((size_t)p * NN + v) * HH + lane];
    int h = lane >> 2;
    float den = 0.f;
    float acc[8] = {};
    int i = beg;
    for (; i + 1 < end; i += 2) {
        int s0 = csr[i], s1 = csr[i + 1];
        float a0v = 0.f, a1v = 0.f;
        if (lane < HH) {
            float e0 = elp[(size_t)s0 * HH + lane] + er_l;
            float e1 = elp[(size_t)s1 * HH + lane] + er_l;
            e0 = e0 > 0.f ? e0 : 0.2f * e0;
            e1 = e1 > 0.f ? e1 : 0.2f * e1;
            a0v = __expf(e0);
            a1v = __expf(e1);
            den += a0v + a1v;
        }
        float ah0 = __shfl_sync(0xffffffffu, a0v, h);
        float ah1 = __shfl_sync(0xffffffffu, a1v, h);
        uint4 r0 = *(const uint4*)(hpp + (size_t)s0 * HFF + (lane << 3));
        uint4 r1 = *(const uint4*)(hpp + (size_t)s1 * HFF + (lane << 3));
        float2 p0 = __half22float2(*(__half2*)&r0.x);
        float2 p1 = __half22float2(*(__half2*)&r0.y);
        float2 p2 = __half22float2(*(__half2*)&r0.z);
        float2 p3 = __half22float2(*(__half2*)&r0.w);
        acc[0] += ah0 * p0.x; acc[1] += ah0 * p0.y;
        acc[2] += ah0 * p1.x; acc[3] += ah0 * p1.y;
        acc[4] += ah0 * p2.x; acc[5] += ah0 * p2.y;
        acc[6] += ah0 * p3.x; acc[7] += ah0 * p3.y;
        float2 q0 = __half22float2(*(__half2*)&r1.x);
        float2 q1 = __half22float2(*(__half2*)&r1.y);
        float2 q2 = __half22float2(*(__half2*)&r1.z);
        float2 q3 = __half22float2(*(__half2*)&r1.w);
        acc[0] += ah1 * q0.x; acc[1] += ah1 * q0.y;
        acc[2] += ah1 * q1.x; acc[3] += ah1 * q1.y;
        acc[4] += ah1 * q2.x; acc[5] += ah1 * q2.y;
        acc[6] += ah1 * q3.x; acc[7] += ah1 * q3.y;
    }
    if (i < end) {
        int s = csr[i];
        float a = 0.f;
        if (lane < HH) {
            float e = elp[(size_t)s * HH + lane] + er_l;
            e = e > 0.f ? e : 0.2f * e;
            a = __expf(e);
            den += a;
        }
        float ah = __shfl_sync(0xffffffffu, a, h);
        uint4 raw = *(const uint4*)(hpp + (size_t)s * HFF + (lane << 3));
        float2 f0 = __half22float2(*(__half2*)&raw.x);
        float2 f1 = __half22float2(*(__half2*)&raw.y);
        float2 f2 = __half22float2(*(__half2*)&raw.z);
        float2 f3 = __half22float2(*(__half2*)&raw.w);
        acc[0] += ah * f0.x; acc[1] += ah * f0.y;
        acc[2] += ah * f1.x; acc[3] += ah * f1.y;
        acc[4] += ah * f2.x; acc[5] += ah * f2.y;
        acc[6] += ah * f3.x; acc[7] += ah * f3.y;
    }
    float dh = __shfl_sync(0xffffffffu, den, h);
    float inv = (end > beg) ? 1.f / dh : 0.f;
    const float* bp = bias + p * HFF + (lane << 3);
    float4 b0 = *(const float4*)(bp);
    float4 b1 = *(const float4*)(bp + 4);
    float o0 = eluf(acc[0] * inv + b0.x);
    float o1 = eluf(acc[1] * inv + b0.y);
    float o2 = eluf(acc[2] * inv + b0.z);
    float o3 = eluf(acc[3] * inv + b0.w);
    float o4 = eluf(acc[4] * inv + b1.x);
    float o5 = eluf(acc[5] * inv + b1.y);
    float o6 = eluf(acc[6] * inv + b1.z);
    float o7 = eluf(acc[7] * inv + b1.w);
    uint4 out;
    *(__half2*)&out.x = __floats2half2_rn(o0, o1);
    *(__half2*)&out.y = __floats2half2_rn(o2, o3);
    *(__half2*)&out.z = __floats2half2_rn(o4, o5);
    *(__half2*)&out.w = __floats2half2_rn(o6, o7);
    *(uint4*)(g_z16 + ((size_t)p * NN + v) * HFF + (lane << 3)) = out;
}

// ---------------- semantic attention GEMM (fp16 HMMA, LDSM + prefetch) ----------
__global__ __launch_bounds__(256, 2) void gemm_sem_f16(const float* __restrict__ b1,
                                                       const float* __restrict__ W2) {
    __shared__ uint32_t As[128][12];
    __shared__ uint32_t Bs[128][12];
    __shared__ float spsum[PP];

    int tid = threadIdx.x;
    int warp = tid >> 5, lane = tid & 31;
    int group = lane >> 2, tid4 = lane & 3;
    int warp_m = (warp >> 2) * 64, warp_n = (warp & 3) * 32;
    int m0 = blockIdx.x * 128;

    if (tid < PP) spsum[tid] = 0.f;

    int mA = tid >> 1, kHalf = (tid & 1) << 3;

    float acc[4][4][4] = {};

    int rowA = m0 + mA;  if (rowA >= MSEM) rowA = MSEM - 1;
    const __half* aPtr = g_z16 + (size_t)rowA * HFF + kHalf;
    const __half* bPtr = g_W1h + (size_t)mA * HFF + kHalf;

    int a_lrow = lane & 15;
    int a_lcol = (lane >> 4) << 2;
    int b_lrow = (lane & 7) + ((lane >> 4) << 3);
    int b_lcol = (lane & 8) ? 4 : 0;
    uint32_t As_base = smem_u32(&As[0][0]);
    uint32_t Bs_base = smem_u32(&Bs[0][0]);

    uint4 av = *(const uint4*)(aPtr);
    uint4 bv = *(const uint4*)(bPtr);

    #pragma unroll
    for (int k0 = 0; k0 < HFF; k0 += 16) {
        __syncthreads();
        *(uint4*)&As[mA][(tid & 1) << 2] = av;
        *(uint4*)&Bs[mA][(tid & 1) << 2] = bv;
        __syncthreads();
        if (k0 + 16 < HFF) {
            av = *(const uint4*)(aPtr + k0 + 16);
            bv = *(const uint4*)(bPtr + k0 + 16);
        }
        uint32_t af[4][4], bf[4][2];
        #pragma unroll
        for (int mi = 0; mi < 4; mi++) {
            int r = warp_m + mi * 16 + a_lrow;
            ldsm_x4(af[mi], As_base + (uint32_t)(r * 12 + a_lcol) * 4u);
        }
        #pragma unroll
        for (int nj = 0; nj < 2; nj++) {
            uint32_t rr[4];
            int r = warp_n + nj * 16 + b_lrow;
            ldsm_x4(rr, Bs_base + (uint32_t)(r * 12 + b_lcol) * 4u);
            bf[2 * nj][0] = rr[0]; bf[2 * nj][1] = rr[1];
            bf[2 * nj + 1][0] = rr[2]; bf[2 * nj + 1][1] = rr[3];
        }
        #pragma unroll
        for (int mi = 0; mi < 4; mi++)
            #pragma unroll
            for (int ni = 0; ni < 4; ni++)
                mma_f16_k16(acc[mi][ni], af[mi], bf[ni]);
    }

    #pragma unroll
    for (int mi = 0; mi < 4; mi++) {
        float s_lo = 0.f, s_hi = 0.f;
        #pragma unroll
        for (int ni = 0; ni < 4; ni++) {
            int col = warp_n + ni * 8 + (tid4 << 1);
            float bb0 = b1[col], bb1 = b1[col + 1];
            float w0 = W2[col], w1 = W2[col + 1];
            s_lo += tanhf(acc[mi][ni][0] + bb0) * w0 + tanhf(acc[mi][ni][1] + bb1) * w1;
            s_hi += tanhf(acc[mi][ni][2] + bb0) * w0 + tanhf(acc[mi][ni][3] + bb1) * w1;
        }
        #pragma unroll
        for (int d = 1; d < 4; d <<= 1) {
            s_lo += __shfl_xor_sync(0xffffffffu, s_lo, d);
            s_hi += __shfl_xor_sync(0xffffffffu, s_hi, d);
        }
        if (tid4 == 0) {
            int r = m0 + warp_m + mi * 16 + group;
            if (r < MSEM)     atomicAdd(&spsum[r / NN], s_lo);
            if (r + 8 < MSEM) atomicAdd(&spsum[(r + 8) / NN], s_hi);
        }
    }
    __syncthreads();
    if (tid < PP) atomicAdd(&g_wsum[tid], spsum[tid]);
}

// ---------------- beta softmax ----------------
__global__ void beta_kernel() {
    if (threadIdx.x == 0 && blockIdx.x == 0) {
        float w[PP], m = -1e30f, s = 0.f;
        #pragma unroll
        for (int p = 0; p < PP; p++) { w[p] = g_wsum[p] / (float)NN; m = fmaxf(m, w[p]); }
        #pragma unroll
        for (int p = 0; p < PP; p++) { w[p] = __expf(w[p] - m); s += w[p]; }
        #pragma unroll
        for (int p = 0; p < PP; p++) g_beta[p] = w[p] / s;
    }
}

// ---------------- fused embedding + per-graph pooling (smem-binned) ----------------
#define POOL_CHUNK 1024
__global__ __launch_bounds__(256) void pool_kernel(const int* __restrict__ gids) {
    __shared__ float bin[BB][64];
    int tid = threadIdx.x;
    int cy = blockIdx.y;
    int n0 = blockIdx.x * POOL_CHUNK;
    #pragma unroll
    for (int k = tid; k < BB * 64; k += 256) ((float*)bin)[k] = 0.f;
    __syncthreads();
    float bb0 = g_beta[0], bb1 = g_beta[1], bb2 = g_beta[2], bb3 = g_beta[3];
    int c = (tid & 15) << 2;
    int colg = cy * 64 + c;
    int nend = n0 + POOL_CHUNK; if (nend > NN) nend = NN;
    for (int n = n0 + (tid >> 4); n < nend; n += 16) {
        int g = gids[n];
        uint2 r0 = *(const uint2*)(g_z16 + ((size_t)0 * NN + n) * HFF + colg);
        uint2 r1 = *(const uint2*)(g_z16 + ((size_t)1 * NN + n) * HFF + colg);
        uint2 r2 = *(const uint2*)(g_z16 + ((size_t)2 * NN + n) * HFF + colg);
        uint2 r3 = *(const uint2*)(g_z16 + ((size_t)3 * NN + n) * HFF + colg);
        float2 a0 = __half22float2(*(__half2*)&r0.x), a1 = __half22float2(*(__half2*)&r0.y);
        float2 b0 = __half22float2(*(__half2*)&r1.x), b1 = __half22float2(*(__half2*)&r1.y);
        float2 c0 = __half22float2(*(__half2*)&r2.x), c1 = __half22float2(*(__half2*)&r2.y);
        float2 d0 = __half22float2(*(__half2*)&r3.x), d1 = __half22float2(*(__half2*)&r3.y);
        float f0 = bb0 * a0.x + bb1 * b0.x + bb2 * c0.x + bb3 * d0.x;
        float f1 = bb0 * a0.y + bb1 * b0.y + bb2 * c0.y + bb3 * d0.y;
        float f2 = bb0 * a1.x + bb1 * b1.x + bb2 * c1.x + bb3 * d1.x;
        float f3 = bb0 * a1.y + bb1 * b1.y + bb2 * c1.y + bb3 * d1.y;
        atomicAdd(&bin[g][c + 0], f0);
        atomicAdd(&bin[g][c + 1], f1);
        atomicAdd(&bin[g][c + 2], f2);
        atomicAdd(&bin[g][c + 3], f3);
    }
    __syncthreads();
    for (int k = tid; k < BB * 64; k += 256) {
        int g = k >> 6, cc = k & 63;
        float v = bin[g][cc];
        if (v != 0.f) atomicAdd(&g_pooled[g * HFF + cy * 64 + cc], v);
    }
}

// ---------------- pooled normalize + classifier ----------------
__global__ __launch_bounds__(256) void final_kernel(const float* __restrict__ clsW,
                                                    const float* __restrict__ clsb,
                                                    float* __restrict__ out) {
    int g = blockIdx.x;
    int t = threadIdx.x;
    float cnt = (float)g_cnt[g];
    float inv = 1.f / fmaxf(cnt, 1.f);
    float pv = g_pooled[g * HFF + t] * inv;
    out[BB * OUTC + g * HFF + t] = pv;
    __shared__ float s0[256], s1[256];
    s0[t] = pv * clsW[t * OUTC + 0];
    s1[t] = pv * clsW[t * OUTC + 1];
    __syncthreads();
    for (int d = 128; d > 0; d >>= 1) {
        if (t < d) { s0[t] += s0[t + d]; s1[t] += s1[t + d]; }
        __syncthreads();
    }
    if (t == 0) {
        out[g * OUTC + 0] = s0[0] + clsb[0];
        out[g * OUTC + 1] = s1[0] + clsb[1];
    }
}

// ---------------- launch ----------------
extern "C" void kernel_launch(void* const* d_in, const int* in_sizes, int n_in,
                              void* d_out, int out_size) {
    const float* h    = (const float*)d_in[0];
    const float* Wg   = (const float*)d_in[1];
    const float* al   = (const float*)d_in[2];
    const float* ar   = (const float*)d_in[3];
    const float* gb   = (const float*)d_in[4];
    const float* sW1  = (const float*)d_in[5];
    const float* sb1  = (const float*)d_in[6];
    const float* sW2  = (const float*)d_in[7];
    const float* cW   = (const float*)d_in[8];
    const float* cb   = (const float*)d_in[9];
    const int*   src  = (const int*)d_in[10];
    const int*   dst  = (const int*)d_in[11];
    const int*   gid  = (const int*)d_in[12];
    float* out = (float*)d_out;

    cvt_zero_kernel<<<(CVT_T1 + CVT_T2 + CVT_T3 + CVT_T4 + 255) / 256, 256>>>(h, Wg, sW1);

    dim3 gp(GPX, 2, PP + 1);
    gemm_proj_tc<<<gp, 256>>>(al, ar, dst, gid);

    bsum_kernel<<<PP * NCH, 256>>>();
    bscan_kernel<<<1, 32>>>();
    cscan_kernel<<<PP * NCH, CH>>>();
    dim3 gd((EE + 255) / 256, PP);
    fill_kernel<<<gd, 256>>>(src, dst);

    dim3 ga(NBLK, PP);
    attn_kernel<<<ga, 256>>>(gb);

    dim3 gs((MSEM + 127) / 128, 1);
    gemm_sem_f16<<<gs, 256>>>(sb1, sW2);

    beta_kernel<<<1, 32>>>();
    dim3 gpool((NN + POOL_CHUNK - 1) / POOL_CHUNK, 4);
    pool_kernel<<<gpool, 256>>>(gid);
    final_kernel<<<BB, 256>>>(cW, cb, out);
}

// round 16
// speedup vs baseline: 1.0316x; 1.0093x over previous
#include <cuda_runtime.h>
#include <cuda_fp16.h>
#include <cstdint>

#define NN   50000
#define PP   4
#define EE   500000
#define IND  128
#define HH   8
#define FF   32
#define HFF  256
#define HSS  128
#define BB   128
#define OUTC 2
#define MSEM (PP * NN)
#define CH   1024
#define NCH  ((NN + CH - 1) / CH)    // 49
#define NBLK ((NN + 7) / 8)
#define GPX  ((NN + 127) / 128)      // proj grid x: 391

// ---------------- persistent device scratch ----------------
__device__ __half    g_hp16[PP * NN * HFF];
__device__ __half    g_z16[PP * NN * HFF];
__device__ __half    g_W1h[HSS * HFF];
__device__ __half    g_h16[NN * IND];
__device__ __half    g_wg16[PP * HFF * IND];
__device__ float g_el[PP * NN * HH];
__device__ float g_er[PP * NN * HH];
__device__ int   g_deg[PP * NN];
__device__ int   g_off[PP * (NN + 1)];
__device__ int   g_cur[PP * NN];
__device__ int   g_csr[PP * EE];
__device__ int   g_bsum[PP * NCH];
__device__ int   g_boff[PP * NCH];
__device__ float g_wsum[PP];
__device__ float g_pooled[BB * HFF];
__device__ int   g_cnt[BB];

__device__ __forceinline__ float eluf(float x) {
    return x > 0.f ? x : (__expf(x) - 1.f);
}

__device__ __forceinline__ void mma_f16_k16(float* c, const uint32_t* a, const uint32_t* b) {
    asm volatile(
        "mma.sync.aligned.m16n8k16.row.col.f32.f16.f16.f32 "
        "{%0,%1,%2,%3},{%4,%5,%6,%7},{%8,%9},{%0,%1,%2,%3};"
        : "+f"(c[0]), "+f"(c[1]), "+f"(c[2]), "+f"(c[3])
        : "r"(a[0]), "r"(a[1]), "r"(a[2]), "r"(a[3]), "r"(b[0]), "r"(b[1]));
}

__device__ __forceinline__ void ldsm_x4(uint32_t* r, uint32_t addr) {
    asm volatile("ldmatrix.sync.aligned.m8n8.x4.shared.b16 {%0,%1,%2,%3}, [%4];"
        : "=r"(r[0]), "=r"(r[1]), "=r"(r[2]), "=r"(r[3]) : "r"(addr));
}

__device__ __forceinline__ uint32_t smem_u32(const void* p) {
    uint32_t a;
    asm("{ .reg .u64 t; cvta.to.shared.u64 t, %1; cvt.u32.u64 %0, t; }" : "=r"(a) : "l"(p));
    return a;
}

// ---------------- fused init + precision conversion ----------------
#define CVT_T1 (NN * IND / 4)
#define CVT_T2 (PP * IND * HFF)
#define CVT_T3 (HFF * HSS)
#define CVT_T4 (PP * NN)
__global__ void cvt_zero_kernel(const float* __restrict__ h, const float* __restrict__ Wg,
                                const float* __restrict__ W1) {
    int i = blockIdx.x * blockDim.x + threadIdx.x;
    if (i < CVT_T1) {
        float4 v = *(const float4*)(h + (size_t)i * 4);
        uint2 u;
        *(__half2*)&u.x = __floats2half2_rn(v.x, v.y);
        *(__half2*)&u.y = __floats2half2_rn(v.z, v.w);
        *(uint2*)(g_h16 + (size_t)i * 4) = u;
    } else if (i < CVT_T1 + CVT_T2) {
        int j = i - CVT_T1;
        int k = j % IND;
        int pn = j / IND;
        int n = pn % HFF;
        int p = pn / HFF;
        g_wg16[j] = __float2half(Wg[((size_t)p * IND + k) * HFF + n]);
    } else if (i < CVT_T1 + CVT_T2 + CVT_T3) {
        int j = i - CVT_T1 - CVT_T2;
        int k = j / HSS, n = j % HSS;
        g_W1h[n * HFF + k] = __float2half(W1[j]);
    } else if (i < CVT_T1 + CVT_T2 + CVT_T3 + CVT_T4) {
        int j = i - CVT_T1 - CVT_T2 - CVT_T3;
        g_deg[j] = 0;
        if (j < BB * HFF) g_pooled[j] = 0.f;
        if (j < BB)       g_cnt[j] = 0;
        if (j < PP)       g_wsum[j] = 0.f;
    }
}

// ---------------- projection GEMM fp16 HMMA + FUSED deg/cnt blocks ----------------
__global__ __launch_bounds__(256, 2) void gemm_proj_tc(const float* __restrict__ al,
                                                       const float* __restrict__ ar,
                                                       const int* __restrict__ dst,
                                                       const int* __restrict__ gids) {
    if (blockIdx.z == PP) {
        int t = (blockIdx.y * gridDim.x + blockIdx.x) * 256 + threadIdx.x;
        int nthr = gridDim.x * 2 * 256;
        if (t < NN) atomicAdd(&g_cnt[gids[t]], 1);
        for (int i = t; i < PP * EE; i += nthr) {
            int p = i / EE;
            atomicAdd(&g_deg[p * NN + dst[i]], 1);
        }
        return;
    }
    int p = blockIdx.z;
    const __half* B = g_wg16 + (size_t)p * HFF * IND;
    __half* C = g_hp16 + (size_t)p * NN * HFF;

    __shared__ uint32_t As[128][12];
    __shared__ uint32_t Bs[128][12];

    int tid = threadIdx.x;
    int warp = tid >> 5, lane = tid & 31;
    int group = lane >> 2, tid4 = lane & 3;
    int warp_m = (warp >> 2) * 64, warp_n = (warp & 3) * 32;
    int m0 = blockIdx.x * 128, n0 = blockIdx.y * 128;

    int mA = tid >> 1, kHalf = (tid & 1) << 3;

    float acc[4][4][4] = {};

    int rowA = m0 + mA;  if (rowA >= NN) rowA = NN - 1;
    const __half* aPtr = g_h16 + (size_t)rowA * IND + kHalf;
    const __half* bPtr = B + (size_t)(n0 + mA) * IND + kHalf;

    int a_lrow = lane & 15;
    int a_lcol = (lane >> 4) << 2;
    int b_lrow = (lane & 7) + ((lane >> 4) << 3);
    int b_lcol = (lane & 8) ? 4 : 0;
    uint32_t As_base = smem_u32(&As[0][0]);
    uint32_t Bs_base = smem_u32(&Bs[0][0]);

    uint4 av = *(const uint4*)(aPtr);
    uint4 bv = *(const uint4*)(bPtr);

    #pragma unroll
    for (int k0 = 0; k0 < IND; k0 += 16) {
        __syncthreads();
        *(uint4*)&As[mA][(tid & 1) << 2] = av;
        *(uint4*)&Bs[mA][(tid & 1) << 2] = bv;
        __syncthreads();
        if (k0 + 16 < IND) {
            av = *(const uint4*)(aPtr + k0 + 16);
            bv = *(const uint4*)(bPtr + k0 + 16);
        }
        uint32_t af[4][4], bf[4][2];
        #pragma unroll
        for (int mi = 0; mi < 4; mi++) {
            int r = warp_m + mi * 16 + a_lrow;
            ldsm_x4(af[mi], As_base + (uint32_t)(r * 12 + a_lcol) * 4u);
        }
        #pragma unroll
        for (int nj = 0; nj < 2; nj++) {
            uint32_t rr[4];
            int r = warp_n + nj * 16 + b_lrow;
            ldsm_x4(rr, Bs_base + (uint32_t)(r * 12 + b_lcol) * 4u);
            bf[2 * nj][0] = rr[0]; bf[2 * nj][1] = rr[1];
            bf[2 * nj + 1][0] = rr[2]; bf[2 * nj + 1][1] = rr[3];
        }
        #pragma unroll
        for (int mi = 0; mi < 4; mi++)
            #pragma unroll
            for (int ni = 0; ni < 4; ni++)
                mma_f16_k16(acc[mi][ni], af[mi], bf[ni]);
    }

    #pragma unroll
    for (int mi = 0; mi < 4; mi++) {
        int r_lo = m0 + warp_m + mi * 16 + group;
        #pragma unroll
        for (int ni = 0; ni < 4; ni++) {
            int col = n0 + warp_n + ni * 8 + (tid4 << 1);
            if (r_lo < NN) {
                __half2 o = __floats2half2_rn(acc[mi][ni][0], acc[mi][ni][1]);
                *(__half2*)(C + (size_t)r_lo * HFF + col) = o;
            }
            if (r_lo + 8 < NN) {
                __half2 o = __floats2half2_rn(acc[mi][ni][2], acc[mi][ni][3]);
                *(__half2*)(C + (size_t)(r_lo + 8) * HFF + col) = o;
            }
        }
    }

    int head = blockIdx.y * 4 + (warp_n >> 5);
    const float* alh = al + p * HFF + head * FF;
    const float* arh = ar + p * HFF + head * FF;
    #pragma unroll
    for (int mi = 0; mi < 4; mi++) {
        float el_lo = 0.f, el_hi = 0.f, er_lo = 0.f, er_hi = 0.f;
        #pragma unroll
        for (int ni = 0; ni < 4; ni++) {
            int f = ni * 8 + (tid4 << 1);
            float a0 = alh[f], a1 = alh[f + 1];
            float r0 = arh[f], r1 = arh[f + 1];
            el_lo += acc[mi][ni][0] * a0 + acc[mi][ni][1] * a1;
            er_lo += acc[mi][ni][0] * r0 + acc[mi][ni][1] * r1;
            el_hi += acc[mi][ni][2] * a0 + acc[mi][ni][3] * a1;
            er_hi += acc[mi][ni][2] * r0 + acc[mi][ni][3] * r1;
        }
        #pragma unroll
        for (int d = 1; d < 4; d <<= 1) {
            el_lo += __shfl_xor_sync(0xffffffffu, el_lo, d);
            er_lo += __shfl_xor_sync(0xffffffffu, er_lo, d);
            el_hi += __shfl_xor_sync(0xffffffffu, el_hi, d);
            er_hi += __shfl_xor_sync(0xffffffffu, er_hi, d);
        }
        if (tid4 == 0) {
            int r = m0 + warp_m + mi * 16 + group;
            if (r < NN) {
                g_el[((size_t)p * NN + r) * HH + head] = el_lo;
                g_er[((size_t)p * NN + r) * HH + head] = er_lo;
            }
            if (r + 8 < NN) {
                g_el[((size_t)p * NN + r + 8) * HH + head] = el_hi;
                g_er[((size_t)p * NN + r + 8) * HH + head] = er_hi;
            }
        }
    }
}

// ---------------- CSR scan + fill ----------------
__global__ void bsum_kernel() {
    __shared__ int sred[256];
    int b = blockIdx.x;
    int p = b / NCH, c = b % NCH;
    int base = c * CH;
    int tid = threadIdx.x;
    int s = 0;
    #pragma unroll
    for (int j = 0; j < CH; j += 256) {
        int i = base + j + tid;
        if (i < NN) s += g_deg[p * NN + i];
    }
    sred[tid] = s;
    __syncthreads();
    for (int d = 128; d > 0; d >>= 1) {
        if (tid < d) sred[tid] += sred[tid + d];
        __syncthreads();
    }
    if (tid == 0) g_bsum[b] = sred[0];
}

// parallel exclusive segmented scan: 64 threads per metapath, Hillis-Steele over 49 sums
__global__ void bscan_kernel() {
    __shared__ int sc[PP][64];
    int t = threadIdx.x;
    int p = t >> 6, c = t & 63;
    int v = (c < NCH) ? g_bsum[p * NCH + c] : 0;
    sc[p][c] = v;
    __syncthreads();
    #pragma unroll
    for (int d = 1; d < 64; d <<= 1) {
        int add = (c >= d) ? sc[p][c - d] : 0;
        __syncthreads();
        sc[p][c] += add;
        __syncthreads();
    }
    if (c < NCH) g_boff[p * NCH + c] = sc[p][c] - v;   // exclusive
}

__global__ void cscan_kernel() {
    __shared__ int wsums[32];
    int b = blockIdx.x;
    int p = b / NCH, c = b % NCH;
    int tid = threadIdx.x, lane = tid & 31, wid = tid >> 5;
    int i = c * CH + tid;
    int v = (i < NN) ? g_deg[p * NN + i] : 0;
    int x = v;
    #pragma unroll
    for (int d = 1; d < 32; d <<= 1) {
        int t2 = __shfl_up_sync(0xffffffffu, x, d);
        if (lane >= d) x += t2;
    }
    if (lane == 31) wsums[wid] = x;
    __syncthreads();
    if (wid == 0) {
        int y = wsums[lane];
        #pragma unroll
        for (int d = 1; d < 32; d <<= 1) {
            int t2 = __shfl_up_sync(0xffffffffu, y, d);
            if (lane >= d) y += t2;
        }
        wsums[lane] = y;
    }
    __syncthreads();
    int incl = x + (wid ? wsums[wid - 1] : 0) + g_boff[b];
    if (i < NN) {
        g_off[p * (NN + 1) + i + 1] = incl;
        g_cur[p * NN + i] = incl - v;
    }
    if (tid == 0 && c == 0) g_off[p * (NN + 1)] = 0;
}

__global__ void fill_kernel(const int* __restrict__ src, const int* __restrict__ dst) {
    int i = blockIdx.x * blockDim.x + threadIdx.x;
    int p = blockIdx.y;
    if (i >= EE) return;
    int d = dst[p * EE + i];
    int slot = atomicAdd(&g_cur[p * NN + d], 1);
    g_csr[p * EE + slot] = src[p * EE + i];
}

// ---------------- GAT edge softmax + aggregation (unroll x2, fp16 gather) ----------------
__global__ __launch_bounds__(256) void attn_kernel(const float* __restrict__ bias) {
    int lane = threadIdx.x & 31;
    int v = blockIdx.x * 8 + (threadIdx.x >> 5);
    if (v >= NN) return;
    int p = blockIdx.y;
    int beg = g_off[p * (NN + 1) + v];
    int end = g_off[p * (NN + 1) + v + 1];
    const float*  __restrict__ elp = g_el + (size_t)p * NN * HH;
    const __half* __restrict__ hpp = g_hp16 + (size_t)p * NN * HFF;
    const int*    __restrict__ csr = g_csr + (size_t)p * EE;
    float er_l = 0.f;
    if (lane < HH) er_l = g_er[((size_t)p * NN + v) * HH + lane];
    int h = lane >> 2;
    float den = 0.f;
    float acc[8] = {};
    int i = beg;
    for (; i + 1 < end; i += 2) {
        int s0 = csr[i], s1 = csr[i + 1];
        float a0v = 0.f, a1v = 0.f;
        if (lane < HH) {
            float e0 = elp[(size_t)s0 * HH + lane] + er_l;
            float e1 = elp[(size_t)s1 * HH + lane] + er_l;
            e0 = e0 > 0.f ? e0 : 0.2f * e0;
            e1 = e1 > 0.f ? e1 : 0.2f * e1;
            a0v = __expf(e0);
            a1v = __expf(e1);
            den += a0v + a1v;
        }
        float ah0 = __shfl_sync(0xffffffffu, a0v, h);
        float ah1 = __shfl_sync(0xffffffffu, a1v, h);
        uint4 r0 = *(const uint4*)(hpp + (size_t)s0 * HFF + (lane << 3));
        uint4 r1 = *(const uint4*)(hpp + (size_t)s1 * HFF + (lane << 3));
        float2 p0 = __half22float2(*(__half2*)&r0.x);
        float2 p1 = __half22float2(*(__half2*)&r0.y);
        float2 p2 = __half22float2(*(__half2*)&r0.z);
        float2 p3 = __half22float2(*(__half2*)&r0.w);
        acc[0] += ah0 * p0.x; acc[1] += ah0 * p0.y;
        acc[2] += ah0 * p1.x; acc[3] += ah0 * p1.y;
        acc[4] += ah0 * p2.x; acc[5] += ah0 * p2.y;
        acc[6] += ah0 * p3.x; acc[7] += ah0 * p3.y;
        float2 q0 = __half22float2(*(__half2*)&r1.x);
        float2 q1 = __half22float2(*(__half2*)&r1.y);
        float2 q2 = __half22float2(*(__half2*)&r1.z);
        float2 q3 = __half22float2(*(__half2*)&r1.w);
        acc[0] += ah1 * q0.x; acc[1] += ah1 * q0.y;
        acc[2] += ah1 * q1.x; acc[3] += ah1 * q1.y;
        acc[4] += ah1 * q2.x; acc[5] += ah1 * q2.y;
        acc[6] += ah1 * q3.x; acc[7] += ah1 * q3.y;
    }
    if (i < end) {
        int s = csr[i];
        float a = 0.f;
        if (lane < HH) {
            float e = elp[(size_t)s * HH + lane] + er_l;
            e = e > 0.f ? e : 0.2f * e;
            a = __expf(e);
            den += a;
        }
        float ah = __shfl_sync(0xffffffffu, a, h);
        uint4 raw = *(const uint4*)(hpp + (size_t)s * HFF + (lane << 3));
        float2 f0 = __half22float2(*(__half2*)&raw.x);
        float2 f1 = __half22float2(*(__half2*)&raw.y);
        float2 f2 = __half22float2(*(__half2*)&raw.z);
        float2 f3 = __half22float2(*(__half2*)&raw.w);
        acc[0] += ah * f0.x; acc[1] += ah * f0.y;
        acc[2] += ah * f1.x; acc[3] += ah * f1.y;
        acc[4] += ah * f2.x; acc[5] += ah * f2.y;
        acc[6] += ah * f3.x; acc[7] += ah * f3.y;
    }
    float dh = __shfl_sync(0xffffffffu, den, h);
    float inv = (end > beg) ? 1.f / dh : 0.f;
    const float* bp = bias + p * HFF + (lane << 3);
    float4 b0 = *(const float4*)(bp);
    float4 b1 = *(const float4*)(bp + 4);
    float o0 = eluf(acc[0] * inv + b0.x);
    float o1 = eluf(acc[1] * inv + b0.y);
    float o2 = eluf(acc[2] * inv + b0.z);
    float o3 = eluf(acc[3] * inv + b0.w);
    float o4 = eluf(acc[4] * inv + b1.x);
    float o5 = eluf(acc[5] * inv + b1.y);
    float o6 = eluf(acc[6] * inv + b1.z);
    float o7 = eluf(acc[7] * inv + b1.w);
    uint4 out;
    *(__half2*)&out.x = __floats2half2_rn(o0, o1);
    *(__half2*)&out.y = __floats2half2_rn(o2, o3);
    *(__half2*)&out.z = __floats2half2_rn(o4, o5);
    *(__half2*)&out.w = __floats2half2_rn(o6, o7);
    *(uint4*)(g_z16 + ((size_t)p * NN + v) * HFF + (lane << 3)) = out;
}

// ---------------- semantic attention GEMM (fp16 HMMA, LDSM + prefetch) ----------
__global__ __launch_bounds__(256, 2) void gemm_sem_f16(const float* __restrict__ b1,
                                                       const float* __restrict__ W2) {
    __shared__ uint32_t As[128][12];
    __shared__ uint32_t Bs[128][12];
    __shared__ float spsum[PP];

    int tid = threadIdx.x;
    int warp = tid >> 5, lane = tid & 31;
    int group = lane >> 2, tid4 = lane & 3;
    int warp_m = (warp >> 2) * 64, warp_n = (warp & 3) * 32;
    int m0 = blockIdx.x * 128;

    if (tid < PP) spsum[tid] = 0.f;

    int mA = tid >> 1, kHalf = (tid & 1) << 3;

    float acc[4][4][4] = {};

    int rowA = m0 + mA;  if (rowA >= MSEM) rowA = MSEM - 1;
    const __half* aPtr = g_z16 + (size_t)rowA * HFF + kHalf;
    const __half* bPtr = g_W1h + (size_t)mA * HFF + kHalf;

    int a_lrow = lane & 15;
    int a_lcol = (lane >> 4) << 2;
    int b_lrow = (lane & 7) + ((lane >> 4) << 3);
    int b_lcol = (lane & 8) ? 4 : 0;
    uint32_t As_base = smem_u32(&As[0][0]);
    uint32_t Bs_base = smem_u32(&Bs[0][0]);

    uint4 av = *(const uint4*)(aPtr);
    uint4 bv = *(const uint4*)(bPtr);

    #pragma unroll
    for (int k0 = 0; k0 < HFF; k0 += 16) {
        __syncthreads();
        *(uint4*)&As[mA][(tid & 1) << 2] = av;
        *(uint4*)&Bs[mA][(tid & 1) << 2] = bv;
        __syncthreads();
        if (k0 + 16 < HFF) {
            av = *(const uint4*)(aPtr + k0 + 16);
            bv = *(const uint4*)(bPtr + k0 + 16);
        }
        uint32_t af[4][4], bf[4][2];
        #pragma unroll
        for (int mi = 0; mi < 4; mi++) {
            int r = warp_m + mi * 16 + a_lrow;
            ldsm_x4(af[mi], As_base + (uint32_t)(r * 12 + a_lcol) * 4u);
        }
        #pragma unroll
        for (int nj = 0; nj < 2; nj++) {
            uint32_t rr[4];
            int r = warp_n + nj * 16 + b_lrow;
            ldsm_x4(rr, Bs_base + (uint32_t)(r * 12 + b_lcol) * 4u);
            bf[2 * nj][0] = rr[0]; bf[2 * nj][1] = rr[1];
            bf[2 * nj + 1][0] = rr[2]; bf[2 * nj + 1][1] = rr[3];
        }
        #pragma unroll
        for (int mi = 0; mi < 4; mi++)
            #pragma unroll
            for (int ni = 0; ni < 4; ni++)
                mma_f16_k16(acc[mi][ni], af[mi], bf[ni]);
    }

    #pragma unroll
    for (int mi = 0; mi < 4; mi++) {
        float s_lo = 0.f, s_hi = 0.f;
        #pragma unroll
        for (int ni = 0; ni < 4; ni++) {
            int col = warp_n + ni * 8 + (tid4 << 1);
            float bb0 = b1[col], bb1 = b1[col + 1];
            float w0 = W2[col], w1 = W2[col + 1];
            s_lo += tanhf(acc[mi][ni][0] + bb0) * w0 + tanhf(acc[mi][ni][1] + bb1) * w1;
            s_hi += tanhf(acc[mi][ni][2] + bb0) * w0 + tanhf(acc[mi][ni][3] + bb1) * w1;
        }
        #pragma unroll
        for (int d = 1; d < 4; d <<= 1) {
            s_lo += __shfl_xor_sync(0xffffffffu, s_lo, d);
            s_hi += __shfl_xor_sync(0xffffffffu, s_hi, d);
        }
        if (tid4 == 0) {
            int r = m0 + warp_m + mi * 16 + group;
            if (r < MSEM)     atomicAdd(&spsum[r / NN], s_lo);
            if (r + 8 < MSEM) atomicAdd(&spsum[(r + 8) / NN], s_hi);
        }
    }
    __syncthreads();
    if (tid < PP) atomicAdd(&g_wsum[tid], spsum[tid]);
}

// ---------------- fused embedding + per-graph pooling (beta computed locally) --------
#define POOL_CHUNK 1024
__global__ __launch_bounds__(256) void pool_kernel(const int* __restrict__ gids) {
    __shared__ float bin[BB][64];
    __shared__ float sbeta[PP];
    int tid = threadIdx.x;
    int cy = blockIdx.y;
    int n0 = blockIdx.x * POOL_CHUNK;
    #pragma unroll
    for (int k = tid; k < BB * 64; k += 256) ((float*)bin)[k] = 0.f;
    if (tid == 0) {
        float w[PP], m = -1e30f, s = 0.f;
        #pragma unroll
        for (int p = 0; p < PP; p++) { w[p] = g_wsum[p] / (float)NN; m = fmaxf(m, w[p]); }
        #pragma unroll
        for (int p = 0; p < PP; p++) { w[p] = __expf(w[p] - m); s += w[p]; }
        #pragma unroll
        for (int p = 0; p < PP; p++) sbeta[p] = w[p] / s;
    }
    __syncthreads();
    float bb0 = sbeta[0], bb1 = sbeta[1], bb2 = sbeta[2], bb3 = sbeta[3];
    int c = (tid & 15) << 2;
    int colg = cy * 64 + c;
    int nend = n0 + POOL_CHUNK; if (nend > NN) nend = NN;
    for (int n = n0 + (tid >> 4); n < nend; n += 16) {
        int g = gids[n];
        uint2 r0 = *(const uint2*)(g_z16 + ((size_t)0 * NN + n) * HFF + colg);
        uint2 r1 = *(const uint2*)(g_z16 + ((size_t)1 * NN + n) * HFF + colg);
        uint2 r2 = *(const uint2*)(g_z16 + ((size_t)2 * NN + n) * HFF + colg);
        uint2 r3 = *(const uint2*)(g_z16 + ((size_t)3 * NN + n) * HFF + colg);
        float2 a0 = __half22float2(*(__half2*)&r0.x), a1 = __half22float2(*(__half2*)&r0.y);
        float2 b0 = __half22float2(*(__half2*)&r1.x), b1 = __half22float2(*(__half2*)&r1.y);
        float2 c0 = __half22float2(*(__half2*)&r2.x), c1 = __half22float2(*(__half2*)&r2.y);
        float2 d0 = __half22float2(*(__half2*)&r3.x), d1 = __half22float2(*(__half2*)&r3.y);
        float f0 = bb0 * a0.x + bb1 * b0.x + bb2 * c0.x + bb3 * d0.x;
        float f1 = bb0 * a0.y + bb1 * b0.y + bb2 * c0.y + bb3 * d0.y;
        float f2 = bb0 * a1.x + bb1 * b1.x + bb2 * c1.x + bb3 * d1.x;
        float f3 = bb0 * a1.y + bb1 * b1.y + bb2 * c1.y + bb3 * d1.y;
        atomicAdd(&bin[g][c + 0], f0);
        atomicAdd(&bin[g][c + 1], f1);
        atomicAdd(&bin[g][c + 2], f2);
        atomicAdd(&bin[g][c + 3], f3);
    }
    __syncthreads();
    for (int k = tid; k < BB * 64; k += 256) {
        int g = k >> 6, cc = k & 63;
        float v = bin[g][cc];
        if (v != 0.f) atomicAdd(&g_pooled[g * HFF + cy * 64 + cc], v);
    }
}

// ---------------- pooled normalize + classifier ----------------
__global__ __launch_bounds__(256) void final_kernel(const float* __restrict__ clsW,
                                                    const float* __restrict__ clsb,
                                                    float* __restrict__ out) {
    int g = blockIdx.x;
    int t = threadIdx.x;
    float cnt = (float)g_cnt[g];
    float inv = 1.f / fmaxf(cnt, 1.f);
    float pv = g_pooled[g * HFF + t] * inv;
    out[BB * OUTC + g * HFF + t] = pv;
    __shared__ float s0[256], s1[256];
    s0[t] = pv * clsW[t * OUTC + 0];
    s1[t] = pv * clsW[t * OUTC + 1];
    __syncthreads();
    for (int d = 128; d > 0; d >>= 1) {
        if (t < d) { s0[t] += s0[t + d]; s1[t] += s1[t + d]; }
        __syncthreads();
    }
    if (t == 0) {
        out[g * OUTC + 0] = s0[0] + clsb[0];
        out[g * OUTC + 1] = s1[0] + clsb[1];
    }
}

// ---------------- launch ----------------
extern "C" void kernel_launch(void* const* d_in, const int* in_sizes, int n_in,
                              void* d_out, int out_size) {
    const float* h    = (const float*)d_in[0];
    const float* Wg   = (const float*)d_in[1];
    const float* al   = (const float*)d_in[2];
    const float* ar   = (const float*)d_in[3];
    const float* gb   = (const float*)d_in[4];
    const float* sW1  = (const float*)d_in[5];
    const float* sb1  = (const float*)d_in[6];
    const float* sW2  = (const float*)d_in[7];
    const float* cW   = (const float*)d_in[8];
    const float* cb   = (const float*)d_in[9];
    const int*   src  = (const int*)d_in[10];
    const int*   dst  = (const int*)d_in[11];
    const int*   gid  = (const int*)d_in[12];
    float* out = (float*)d_out;

    cvt_zero_kernel<<<(CVT_T1 + CVT_T2 + CVT_T3 + CVT_T4 + 255) / 256, 256>>>(h, Wg, sW1);

    dim3 gp(GPX, 2, PP + 1);
    gemm_proj_tc<<<gp, 256>>>(al, ar, dst, gid);

    bsum_kernel<<<PP * NCH, 256>>>();
    bscan_kernel<<<1, PP * 64>>>();
    cscan_kernel<<<PP * NCH, CH>>>();
    dim3 gd((EE + 255) / 256, PP);
    fill_kernel<<<gd, 256>>>(src, dst);

    dim3 ga(NBLK, PP);
    attn_kernel<<<ga, 256>>>(gb);

    dim3 gs((MSEM + 127) / 128, 1);
    gemm_sem_f16<<<gs, 256>>>(sb1, sW2);

    dim3 gpool((NN + POOL_CHUNK - 1) / POOL_CHUNK, 4);
    pool_kernel<<<gpool, 256>>>(gid);
    final_kernel<<<BB, 256>>>(cW, cb, out);
}

// round 17
// speedup vs baseline: 1.0398x; 1.0080x over previous
#include <cuda_runtime.h>
#include <cuda_fp16.h>
#include <cstdint>

#define NN   50000
#define PP   4
#define EE   500000
#define IND  128
#define HH   8
#define FF   32
#define HFF  256
#define HSS  128
#define BB   128
#define OUTC 2
#define MSEM (PP * NN)
#define CH   1024
#define NCH  ((NN + CH - 1) / CH)    // 49
#define NBLK ((NN + 7) / 8)
#define GPX  ((NN + 127) / 128)      // proj grid x: 391

// ---------------- persistent device scratch ----------------
__device__ __half    g_hp16[PP * NN * HFF];
__device__ __half    g_z16[PP * NN * HFF];
__device__ __half    g_W1h[HSS * HFF];
__device__ __half    g_h16[NN * IND];
__device__ __half    g_wg16[PP * HFF * IND];
__device__ float g_el[PP * NN * HH];
__device__ float g_er[PP * NN * HH];
__device__ int   g_deg[PP * NN];
__device__ int   g_off[PP * (NN + 1)];
__device__ int   g_cur[PP * NN];
__device__ int   g_csr[PP * EE];
__device__ float g_wsum[PP];
__device__ float g_pooled[BB * HFF];
__device__ int   g_cnt[BB];

__device__ __forceinline__ float eluf(float x) {
    return x > 0.f ? x : (__expf(x) - 1.f);
}

__device__ __forceinline__ void mma_f16_k16(float* c, const uint32_t* a, const uint32_t* b) {
    asm volatile(
        "mma.sync.aligned.m16n8k16.row.col.f32.f16.f16.f32 "
        "{%0,%1,%2,%3},{%4,%5,%6,%7},{%8,%9},{%0,%1,%2,%3};"
        : "+f"(c[0]), "+f"(c[1]), "+f"(c[2]), "+f"(c[3])
        : "r"(a[0]), "r"(a[1]), "r"(a[2]), "r"(a[3]), "r"(b[0]), "r"(b[1]));
}

__device__ __forceinline__ void ldsm_x4(uint32_t* r, uint32_t addr) {
    asm volatile("ldmatrix.sync.aligned.m8n8.x4.shared.b16 {%0,%1,%2,%3}, [%4];"
        : "=r"(r[0]), "=r"(r[1]), "=r"(r[2]), "=r"(r[3]) : "r"(addr));
}

__device__ __forceinline__ uint32_t smem_u32(const void* p) {
    uint32_t a;
    asm("{ .reg .u64 t; cvta.to.shared.u64 t, %1; cvt.u32.u64 %0, t; }" : "=r"(a) : "l"(p));
    return a;
}

// ---------------- fused init + precision conversion ----------------
#define CVT_T1 (NN * IND / 4)
#define CVT_T2 (PP * IND * HFF)
#define CVT_T3 (HFF * HSS)
#define CVT_T4 (PP * NN)
__global__ void cvt_zero_kernel(const float* __restrict__ h, const float* __restrict__ Wg,
                                const float* __restrict__ W1) {
    int i = blockIdx.x * blockDim.x + threadIdx.x;
    if (i < CVT_T1) {
        float4 v = *(const float4*)(h + (size_t)i * 4);
        uint2 u;
        *(__half2*)&u.x = __floats2half2_rn(v.x, v.y);
        *(__half2*)&u.y = __floats2half2_rn(v.z, v.w);
        *(uint2*)(g_h16 + (size_t)i * 4) = u;
    } else if (i < CVT_T1 + CVT_T2) {
        int j = i - CVT_T1;
        int k = j % IND;
        int pn = j / IND;
        int n = pn % HFF;
        int p = pn / HFF;
        g_wg16[j] = __float2half(Wg[((size_t)p * IND + k) * HFF + n]);
    } else if (i < CVT_T1 + CVT_T2 + CVT_T3) {
        int j = i - CVT_T1 - CVT_T2;
        int k = j / HSS, n = j % HSS;
        g_W1h[n * HFF + k] = __float2half(W1[j]);
    } else if (i < CVT_T1 + CVT_T2 + CVT_T3 + CVT_T4) {
        int j = i - CVT_T1 - CVT_T2 - CVT_T3;
        g_deg[j] = 0;
        if (j < BB * HFF) g_pooled[j] = 0.f;
        if (j < BB)       g_cnt[j] = 0;
        if (j < PP)       g_wsum[j] = 0.f;
    }
}

// ---------------- projection GEMM fp16 HMMA + FUSED deg/cnt blocks ----------------
__global__ __launch_bounds__(256, 2) void gemm_proj_tc(const float* __restrict__ al,
                                                       const float* __restrict__ ar,
                                                       const int* __restrict__ dst,
                                                       const int* __restrict__ gids) {
    if (blockIdx.z == PP) {
        int t = (blockIdx.y * gridDim.x + blockIdx.x) * 256 + threadIdx.x;
        int nthr = gridDim.x * 2 * 256;
        if (t < NN) atomicAdd(&g_cnt[gids[t]], 1);
        for (int i = t; i < PP * EE; i += nthr) {
            int p = i / EE;
            atomicAdd(&g_deg[p * NN + dst[i]], 1);
        }
        return;
    }
    int p = blockIdx.z;
    const __half* B = g_wg16 + (size_t)p * HFF * IND;
    __half* C = g_hp16 + (size_t)p * NN * HFF;

    __shared__ uint32_t As[128][12];
    __shared__ uint32_t Bs[128][12];

    int tid = threadIdx.x;
    int warp = tid >> 5, lane = tid & 31;
    int group = lane >> 2, tid4 = lane & 3;
    int warp_m = (warp >> 2) * 64, warp_n = (warp & 3) * 32;
    int m0 = blockIdx.x * 128, n0 = blockIdx.y * 128;

    int mA = tid >> 1, kHalf = (tid & 1) << 3;

    float acc[4][4][4] = {};

    int rowA = m0 + mA;  if (rowA >= NN) rowA = NN - 1;
    const __half* aPtr = g_h16 + (size_t)rowA * IND + kHalf;
    const __half* bPtr = B + (size_t)(n0 + mA) * IND + kHalf;

    int a_lrow = lane & 15;
    int a_lcol = (lane >> 4) << 2;
    int b_lrow = (lane & 7) + ((lane >> 4) << 3);
    int b_lcol = (lane & 8) ? 4 : 0;
    uint32_t As_base = smem_u32(&As[0][0]);
    uint32_t Bs_base = smem_u32(&Bs[0][0]);

    uint4 av = *(const uint4*)(aPtr);
    uint4 bv = *(const uint4*)(bPtr);

    #pragma unroll
    for (int k0 = 0; k0 < IND; k0 += 16) {
        __syncthreads();
        *(uint4*)&As[mA][(tid & 1) << 2] = av;
        *(uint4*)&Bs[mA][(tid & 1) << 2] = bv;
        __syncthreads();
        if (k0 + 16 < IND) {
            av = *(const uint4*)(aPtr + k0 + 16);
            bv = *(const uint4*)(bPtr + k0 + 16);
        }
        uint32_t af[4][4], bf[4][2];
        #pragma unroll
        for (int mi = 0; mi < 4; mi++) {
            int r = warp_m + mi * 16 + a_lrow;
            ldsm_x4(af[mi], As_base + (uint32_t)(r * 12 + a_lcol) * 4u);
        }
        #pragma unroll
        for (int nj = 0; nj < 2; nj++) {
            uint32_t rr[4];
            int r = warp_n + nj * 16 + b_lrow;
            ldsm_x4(rr, Bs_base + (uint32_t)(r * 12 + b_lcol) * 4u);
            bf[2 * nj][0] = rr[0]; bf[2 * nj][1] = rr[1];
            bf[2 * nj + 1][0] = rr[2]; bf[2 * nj + 1][1] = rr[3];
        }
        #pragma unroll
        for (int mi = 0; mi < 4; mi++)
            #pragma unroll
            for (int ni = 0; ni < 4; ni++)
                mma_f16_k16(acc[mi][ni], af[mi], bf[ni]);
    }

    #pragma unroll
    for (int mi = 0; mi < 4; mi++) {
        int r_lo = m0 + warp_m + mi * 16 + group;
        #pragma unroll
        for (int ni = 0; ni < 4; ni++) {
            int col = n0 + warp_n + ni * 8 + (tid4 << 1);
            if (r_lo < NN) {
                __half2 o = __floats2half2_rn(acc[mi][ni][0], acc[mi][ni][1]);
                *(__half2*)(C + (size_t)r_lo * HFF + col) = o;
            }
            if (r_lo + 8 < NN) {
                __half2 o = __floats2half2_rn(acc[mi][ni][2], acc[mi][ni][3]);
                *(__half2*)(C + (size_t)(r_lo + 8) * HFF + col) = o;
            }
        }
    }

    int head = blockIdx.y * 4 + (warp_n >> 5);
    const float* alh = al + p * HFF + head * FF;
    const float* arh = ar + p * HFF + head * FF;
    #pragma unroll
    for (int mi = 0; mi < 4; mi++) {
        float el_lo = 0.f, el_hi = 0.f, er_lo = 0.f, er_hi = 0.f;
        #pragma unroll
        for (int ni = 0; ni < 4; ni++) {
            int f = ni * 8 + (tid4 << 1);
            float a0 = alh[f], a1 = alh[f + 1];
            float r0 = arh[f], r1 = arh[f + 1];
            el_lo += acc[mi][ni][0] * a0 + acc[mi][ni][1] * a1;
            er_lo += acc[mi][ni][0] * r0 + acc[mi][ni][1] * r1;
            el_hi += acc[mi][ni][2] * a0 + acc[mi][ni][3] * a1;
            er_hi += acc[mi][ni][2] * r0 + acc[mi][ni][3] * r1;
        }
        #pragma unroll
        for (int d = 1; d < 4; d <<= 1) {
            el_lo += __shfl_xor_sync(0xffffffffu, el_lo, d);
            er_lo += __shfl_xor_sync(0xffffffffu, er_lo, d);
            el_hi += __shfl_xor_sync(0xffffffffu, el_hi, d);
            er_hi += __shfl_xor_sync(0xffffffffu, er_hi, d);
        }
        if (tid4 == 0) {
            int r = m0 + warp_m + mi * 16 + group;
            if (r < NN) {
                g_el[((size_t)p * NN + r) * HH + head] = el_lo;
                g_er[((size_t)p * NN + r) * HH + head] = er_lo;
            }
            if (r + 8 < NN) {
                g_el[((size_t)p * NN + r + 8) * HH + head] = el_hi;
                g_er[((size_t)p * NN + r + 8) * HH + head] = er_hi;
            }
        }
    }
}

// ---------------- fused single-pass CSR scan ----------------
// block (p,c): boff = block-reduced sum of deg[p][0 .. c*CH); then local scan.
__global__ void cscan_kernel() {
    __shared__ int wsums[32];
    __shared__ int red[32];
    int b = blockIdx.x;
    int p = b / NCH, c = b % NCH;
    int tid = threadIdx.x, lane = tid & 31, wid = tid >> 5;
    const int* degp = g_deg + p * NN;

    // 1) chunk offset: sum of all earlier chunks (L2-resident redundant read)
    int s = 0;
    int lim = c * CH;
    for (int j = tid; j < lim; j += CH) s += degp[j];
    #pragma unroll
    for (int d = 16; d > 0; d >>= 1) s += __shfl_xor_sync(0xffffffffu, s, d);
    if (lane == 0) red[wid] = s;
    __syncthreads();
    if (wid == 0) {
        int y = red[lane];
        #pragma unroll
        for (int d = 16; d > 0; d >>= 1) y += __shfl_xor_sync(0xffffffffu, y, d);
        if (lane == 0) red[0] = y;
    }
    __syncthreads();
    int boff = red[0];

    // 2) local block scan
    int i = c * CH + tid;
    int v = (i < NN) ? degp[i] : 0;
    int x = v;
    #pragma unroll
    for (int d = 1; d < 32; d <<= 1) {
        int t2 = __shfl_up_sync(0xffffffffu, x, d);
        if (lane >= d) x += t2;
    }
    if (lane == 31) wsums[wid] = x;
    __syncthreads();
    if (wid == 0) {
        int y = wsums[lane];
        #pragma unroll
        for (int d = 1; d < 32; d <<= 1) {
            int t2 = __shfl_up_sync(0xffffffffu, y, d);
            if (lane >= d) y += t2;
        }
        wsums[lane] = y;
    }
    __syncthreads();
    int incl = x + (wid ? wsums[wid - 1] : 0) + boff;
    if (i < NN) {
        g_off[p * (NN + 1) + i + 1] = incl;
        g_cur[p * NN + i] = incl - v;
    }
    if (tid == 0 && c == 0) g_off[p * (NN + 1)] = 0;
}

__global__ void fill_kernel(const int* __restrict__ src, const int* __restrict__ dst) {
    int i = blockIdx.x * blockDim.x + threadIdx.x;
    int p = blockIdx.y;
    if (i >= EE) return;
    int d = dst[p * EE + i];
    int slot = atomicAdd(&g_cur[p * NN + d], 1);
    g_csr[p * EE + slot] = src[p * EE + i];
}

// ---------------- GAT edge softmax + aggregation (unroll x2, fp16 gather) ----------------
__global__ __launch_bounds__(256) void attn_kernel(const float* __restrict__ bias) {
    int lane = threadIdx.x & 31;
    int v = blockIdx.x * 8 + (threadIdx.x >> 5);
    if (v >= NN) return;
    int p = blockIdx.y;
    int beg = g_off[p * (NN + 1) + v];
    int end = g_off[p * (NN + 1) + v + 1];
    const float*  __restrict__ elp = g_el + (size_t)p * NN * HH;
    const __half* __restrict__ hpp = g_hp16 + (size_t)p * NN * HFF;
    const int*    __restrict__ csr = g_csr + (size_t)p * EE;
    float er_l = 0.f;
    if (lane < HH) er_l = g_er[((size_t)p * NN + v) * HH + lane];
    int h = lane >> 2;
    float den = 0.f;
    float acc[8] = {};
    int i = beg;
    for (; i + 1 < end; i += 2) {
        int s0 = csr[i], s1 = csr[i + 1];
        float a0v = 0.f, a1v = 0.f;
        if (lane < HH) {
            float e0 = elp[(size_t)s0 * HH + lane] + er_l;
            float e1 = elp[(size_t)s1 * HH + lane] + er_l;
            e0 = e0 > 0.f ? e0 : 0.2f * e0;
            e1 = e1 > 0.f ? e1 : 0.2f * e1;
            a0v = __expf(e0);
            a1v = __expf(e1);
            den += a0v + a1v;
        }
        float ah0 = __shfl_sync(0xffffffffu, a0v, h);
        float ah1 = __shfl_sync(0xffffffffu, a1v, h);
        uint4 r0 = *(const uint4*)(hpp + (size_t)s0 * HFF + (lane << 3));
        uint4 r1 = *(const uint4*)(hpp + (size_t)s1 * HFF + (lane << 3));
        float2 p0 = __half22float2(*(__half2*)&r0.x);
        float2 p1 = __half22float2(*(__half2*)&r0.y);
        float2 p2 = __half22float2(*(__half2*)&r0.z);
        float2 p3 = __half22float2(*(__half2*)&r0.w);
        acc[0] += ah0 * p0.x; acc[1] += ah0 * p0.y;
        acc[2] += ah0 * p1.x; acc[3] += ah0 * p1.y;
        acc[4] += ah0 * p2.x; acc[5] += ah0 * p2.y;
        acc[6] += ah0 * p3.x; acc[7] += ah0 * p3.y;
        float2 q0 = __half22float2(*(__half2*)&r1.x);
        float2 q1 = __half22float2(*(__half2*)&r1.y);
        float2 q2 = __half22float2(*(__half2*)&r1.z);
        float2 q3 = __half22float2(*(__half2*)&r1.w);
        acc[0] += ah1 * q0.x; acc[1] += ah1 * q0.y;
        acc[2] += ah1 * q1.x; acc[3] += ah1 * q1.y;
        acc[4] += ah1 * q2.x; acc[5] += ah1 * q2.y;
        acc[6] += ah1 * q3.x; acc[7] += ah1 * q3.y;
    }
    if (i < end) {
        int s = csr[i];
        float a = 0.f;
        if (lane < HH) {
            float e = elp[(size_t)s * HH + lane] + er_l;
            e = e > 0.f ? e : 0.2f * e;
            a = __expf(e);
            den += a;
        }
        float ah = __shfl_sync(0xffffffffu, a, h);
        uint4 raw = *(const uint4*)(hpp + (size_t)s * HFF + (lane << 3));
        float2 f0 = __half22float2(*(__half2*)&raw.x);
        float2 f1 = __half22float2(*(__half2*)&raw.y);
        float2 f2 = __half22float2(*(__half2*)&raw.z);
        float2 f3 = __half22float2(*(__half2*)&raw.w);
        acc[0] += ah * f0.x; acc[1] += ah * f0.y;
        acc[2] += ah * f1.x; acc[3] += ah * f1.y;
        acc[4] += ah * f2.x; acc[5] += ah * f2.y;
        acc[6] += ah * f3.x; acc[7] += ah * f3.y;
    }
    float dh = __shfl_sync(0xffffffffu, den, h);
    float inv = (end > beg) ? 1.f / dh : 0.f;
    const float* bp = bias + p * HFF + (lane << 3);
    float4 b0 = *(const float4*)(bp);
    float4 b1 = *(const float4*)(bp + 4);
    float o0 = eluf(acc[0] * inv + b0.x);
    float o1 = eluf(acc[1] * inv + b0.y);
    float o2 = eluf(acc[2] * inv + b0.z);
    float o3 = eluf(acc[3] * inv + b0.w);
    float o4 = eluf(acc[4] * inv + b1.x);
    float o5 = eluf(acc[5] * inv + b1.y);
    float o6 = eluf(acc[6] * inv + b1.z);
    float o7 = eluf(acc[7] * inv + b1.w);
    uint4 out;
    *(__half2*)&out.x = __floats2half2_rn(o0, o1);
    *(__half2*)&out.y = __floats2half2_rn(o2, o3);
    *(__half2*)&out.z = __floats2half2_rn(o4, o5);
    *(__half2*)&out.w = __floats2half2_rn(o6, o7);
    *(uint4*)(g_z16 + ((size_t)p * NN + v) * HFF + (lane << 3)) = out;
}

// ---------------- semantic attention GEMM (fp16 HMMA, LDSM + prefetch) ----------
__global__ __launch_bounds__(256, 2) void gemm_sem_f16(const float* __restrict__ b1,
                                                       const float* __restrict__ W2) {
    __shared__ uint32_t As[128][12];
    __shared__ uint32_t Bs[128][12];
    __shared__ float spsum[PP];

    int tid = threadIdx.x;
    int warp = tid >> 5, lane = tid & 31;
    int group = lane >> 2, tid4 = lane & 3;
    int warp_m = (warp >> 2) * 64, warp_n = (warp & 3) * 32;
    int m0 = blockIdx.x * 128;

    if (tid < PP) spsum[tid] = 0.f;

    int mA = tid >> 1, kHalf = (tid & 1) << 3;

    float acc[4][4][4] = {};

    int rowA = m0 + mA;  if (rowA >= MSEM) rowA = MSEM - 1;
    const __half* aPtr = g_z16 + (size_t)rowA * HFF + kHalf;
    const __half* bPtr = g_W1h + (size_t)mA * HFF + kHalf;

    int a_lrow = lane & 15;
    int a_lcol = (lane >> 4) << 2;
    int b_lrow = (lane & 7) + ((lane >> 4) << 3);
    int b_lcol = (lane & 8) ? 4 : 0;
    uint32_t As_base = smem_u32(&As[0][0]);
    uint32_t Bs_base = smem_u32(&Bs[0][0]);

    uint4 av = *(const uint4*)(aPtr);
    uint4 bv = *(const uint4*)(bPtr);

    #pragma unroll
    for (int k0 = 0; k0 < HFF; k0 += 16) {
        __syncthreads();
        *(uint4*)&As[mA][(tid & 1) << 2] = av;
        *(uint4*)&Bs[mA][(tid & 1) << 2] = bv;
        __syncthreads();
        if (k0 + 16 < HFF) {
            av = *(const uint4*)(aPtr + k0 + 16);
            bv = *(const uint4*)(bPtr + k0 + 16);
        }
        uint32_t af[4][4], bf[4][2];
        #pragma unroll
        for (int mi = 0; mi < 4; mi++) {
            int r = warp_m + mi * 16 + a_lrow;
            ldsm_x4(af[mi], As_base + (uint32_t)(r * 12 + a_lcol) * 4u);
        }
        #pragma unroll
        for (int nj = 0; nj < 2; nj++) {
            uint32_t rr[4];
            int r = warp_n + nj * 16 + b_lrow;
            ldsm_x4(rr, Bs_base + (uint32_t)(r * 12 + b_lcol) * 4u);
            bf[2 * nj][0] = rr[0]; bf[2 * nj][1] = rr[1];
            bf[2 * nj + 1][0] = rr[2]; bf[2 * nj + 1][1] = rr[3];
        }
        #pragma unroll
        for (int mi = 0; mi < 4; mi++)
            #pragma unroll
            for (int ni = 0; ni < 4; ni++)
                mma_f16_k16(acc[mi][ni], af[mi], bf[ni]);
    }

    #pragma unroll
    for (int mi = 0; mi < 4; mi++) {
        float s_lo = 0.f, s_hi = 0.f;
        #pragma unroll
        for (int ni = 0; ni < 4; ni++) {
            int col = warp_n + ni * 8 + (tid4 << 1);
            float bb0 = b1[col], bb1 = b1[col + 1];
            float w0 = W2[col], w1 = W2[col + 1];
            s_lo += tanhf(acc[mi][ni][0] + bb0) * w0 + tanhf(acc[mi][ni][1] + bb1) * w1;
            s_hi += tanhf(acc[mi][ni][2] + bb0) * w0 + tanhf(acc[mi][ni][3] + bb1) * w1;
        }
        #pragma unroll
        for (int d = 1; d < 4; d <<= 1) {
            s_lo += __shfl_xor_sync(0xffffffffu, s_lo, d);
            s_hi += __shfl_xor_sync(0xffffffffu, s_hi, d);
        }
        if (tid4 == 0) {
            int r = m0 + warp_m + mi * 16 + group;
            if (r < MSEM)     atomicAdd(&spsum[r / NN], s_lo);
            if (r + 8 < MSEM) atomicAdd(&spsum[(r + 8) / NN], s_hi);
        }
    }
    __syncthreads();
    if (tid < PP) atomicAdd(&g_wsum[tid], spsum[tid]);
}

// ---------------- fused embedding + per-graph pooling (beta computed locally) --------
#define POOL_CHUNK 1024
__global__ __launch_bounds__(256) void pool_kernel(const int* __restrict__ gids) {
    __shared__ float bin[BB][64];
    __shared__ float sbeta[PP];
    int tid = threadIdx.x;
    int cy = blockIdx.y;
    int n0 = blockIdx.x * POOL_CHUNK;
    #pragma unroll
    for (int k = tid; k < BB * 64; k += 256) ((float*)bin)[k] = 0.f;
    if (tid == 0) {
        float w[PP], m = -1e30f, s = 0.f;
        #pragma unroll
        for (int p = 0; p < PP; p++) { w[p] = g_wsum[p] / (float)NN; m = fmaxf(m, w[p]); }
        #pragma unroll
        for (int p = 0; p < PP; p++) { w[p] = __expf(w[p] - m); s += w[p]; }
        #pragma unroll
        for (int p = 0; p < PP; p++) sbeta[p] = w[p] / s;
    }
    __syncthreads();
    float bb0 = sbeta[0], bb1 = sbeta[1], bb2 = sbeta[2], bb3 = sbeta[3];
    int c = (tid & 15) << 2;
    int colg = cy * 64 + c;
    int nend = n0 + POOL_CHUNK; if (nend > NN) nend = NN;
    for (int n = n0 + (tid >> 4); n < nend; n += 16) {
        int g = gids[n];
        uint2 r0 = *(const uint2*)(g_z16 + ((size_t)0 * NN + n) * HFF + colg);
        uint2 r1 = *(const uint2*)(g_z16 + ((size_t)1 * NN + n) * HFF + colg);
        uint2 r2 = *(const uint2*)(g_z16 + ((size_t)2 * NN + n) * HFF + colg);
        uint2 r3 = *(const uint2*)(g_z16 + ((size_t)3 * NN + n) * HFF + colg);
        float2 a0 = __half22float2(*(__half2*)&r0.x), a1 = __half22float2(*(__half2*)&r0.y);
        float2 b0 = __half22float2(*(__half2*)&r1.x), b1 = __half22float2(*(__half2*)&r1.y);
        float2 c0 = __half22float2(*(__half2*)&r2.x), c1 = __half22float2(*(__half2*)&r2.y);
        float2 d0 = __half22float2(*(__half2*)&r3.x), d1 = __half22float2(*(__half2*)&r3.y);
        float f0 = bb0 * a0.x + bb1 * b0.x + bb2 * c0.x + bb3 * d0.x;
        float f1 = bb0 * a0.y + bb1 * b0.y + bb2 * c0.y + bb3 * d0.y;
        float f2 = bb0 * a1.x + bb1 * b1.x + bb2 * c1.x + bb3 * d1.x;
        float f3 = bb0 * a1.y + bb1 * b1.y + bb2 * c1.y + bb3 * d1.y;
        atomicAdd(&bin[g][c + 0], f0);
        atomicAdd(&bin[g][c + 1], f1);
        atomicAdd(&bin[g][c + 2], f2);
        atomicAdd(&bin[g][c + 3], f3);
    }
    __syncthreads();
    for (int k = tid; k < BB * 64; k += 256) {
        int g = k >> 6, cc = k & 63;
        float v = bin[g][cc];
        if (v != 0.f) atomicAdd(&g_pooled[g * HFF + cy * 64 + cc], v);
    }
}

// ---------------- pooled normalize + classifier ----------------
__global__ __launch_bounds__(256) void final_kernel(const float* __restrict__ clsW,
                                                    const float* __restrict__ clsb,
                                                    float* __restrict__ out) {
    int g = blockIdx.x;
    int t = threadIdx.x;
    float cnt = (float)g_cnt[g];
    float inv = 1.f / fmaxf(cnt, 1.f);
    float pv = g_pooled[g * HFF + t] * inv;
    out[BB * OUTC + g * HFF + t] = pv;
    __shared__ float s0[256], s1[256];
    s0[t] = pv * clsW[t * OUTC + 0];
    s1[t] = pv * clsW[t * OUTC + 1];
    __syncthreads();
    for (int d = 128; d > 0; d >>= 1) {
        if (t < d) { s0[t] += s0[t + d]; s1[t] += s1[t + d]; }
        __syncthreads();
    }
    if (t == 0) {
        out[g * OUTC + 0] = s0[0] + clsb[0];
        out[g * OUTC + 1] = s1[0] + clsb[1];
    }
}

// ---------------- launch ----------------
extern "C" void kernel_launch(void* const* d_in, const int* in_sizes, int n_in,
                              void* d_out, int out_size) {
    const float* h    = (const float*)d_in[0];
    const float* Wg   = (const float*)d_in[1];
    const float* al   = (const float*)d_in[2];
    const float* ar   = (const float*)d_in[3];
    const float* gb   = (const float*)d_in[4];
    const float* sW1  = (const float*)d_in[5];
    const float* sb1  = (const float*)d_in[6];
    const float* sW2  = (const float*)d_in[7];
    const float* cW   = (const float*)d_in[8];
    const float* cb   = (const float*)d_in[9];
    const int*   src  = (const int*)d_in[10];
    const int*   dst  = (const int*)d_in[11];
    const int*   gid  = (const int*)d_in[12];
    float* out = (float*)d_out;

    cvt_zero_kernel<<<(CVT_T1 + CVT_T2 + CVT_T3 + CVT_T4 + 255) / 256, 256>>>(h, Wg, sW1);

    dim3 gp(GPX, 2, PP + 1);
    gemm_proj_tc<<<gp, 256>>>(al, ar, dst, gid);

    cscan_kernel<<<PP * NCH, CH>>>();
    dim3 gd((EE + 255) / 256, PP);
    fill_kernel<<<gd, 256>>>(src, dst);

    dim3 ga(NBLK, PP);
    attn_kernel<<<ga, 256>>>(gb);

    dim3 gs((MSEM + 127) / 128, 1);
    gemm_sem_f16<<<gs, 256>>>(sb1, sW2);

    dim3 gpool((NN + POOL_CHUNK - 1) / POOL_CHUNK, 4);
    pool_kernel<<<gpool, 256>>>(gid);
    final_kernel<<<BB, 256>>>(cW, cb, out);
}